// round 6
// baseline (speedup 1.0000x reference)
#include <cuda_runtime.h>
#include <cuda_bf16.h>
#include <cstdint>

#define NLAYERS 2
#define NB 4
#define BS 256
#define NHID 1024
#define NINP 1024
#define NTOK 32000
#define T 64
#define B 64
#define DK 16
#define NCTA 128

// ---------------- scratch (device globals: no allocation allowed) ----------
__device__ float g_xbuf[2][(size_t)T * B * NHID];
__device__ float g_xg[(size_t)T * B * NB * 4 * BS];
__device__ float g_h[B * NHID];
__device__ float g_hl[B * NHID];

// grid barrier state (persists across launches; sense-reversing, self-resetting)
__device__ unsigned g_bar_cnt = 0;
__device__ volatile unsigned g_bar_gen = 0;

__device__ __forceinline__ void grid_bar() {
    __threadfence();
    __syncthreads();
    if (threadIdx.x == 0) {
        unsigned g = g_bar_gen;
        if (atomicAdd(&g_bar_cnt, 1u) == NCTA - 1) {
            g_bar_cnt = 0;
            __threadfence();
            g_bar_gen = g + 1;
        } else {
            while (g_bar_gen == g) {}
        }
    }
    __syncthreads();
}

// ---------------- f32x2 helpers ---------------------------------------------
__device__ __forceinline__ unsigned long long splat2(float a) {
    unsigned long long r;
    unsigned int u = __float_as_uint(a);
    asm("mov.b64 %0, {%1, %1};" : "=l"(r) : "r"(u));
    return r;
}
__device__ __forceinline__ unsigned long long pack2(float x, float y) {
    unsigned long long r;
    asm("mov.b64 %0, {%1, %2};" : "=l"(r)
        : "r"(__float_as_uint(x)), "r"(__float_as_uint(y)));
    return r;
}
__device__ __forceinline__ void ffma2(unsigned long long &c, unsigned long long a,
                                      unsigned long long b) {
    asm("fma.rn.f32x2 %0, %1, %2, %0;" : "+l"(c) : "l"(a), "l"(b));
}
__device__ __forceinline__ float2 unpk(unsigned long long v) {
    unsigned int x, y;
    asm("mov.b64 {%0, %1}, %2;" : "=r"(x), "=r"(y) : "l"(v));
    return make_float2(__uint_as_float(x), __uint_as_float(y));
}
__device__ __forceinline__ float sigmoidf_(float x) { return 1.f / (1.f + expf(-x)); }

// ---------------- bf16 split helpers ----------------------------------------
__device__ __forceinline__ uint32_t pkbf(float a, float b) {
    __nv_bfloat162 t = __floats2bfloat162_rn(a, b);
    return *reinterpret_cast<uint32_t*>(&t);
}
__device__ __forceinline__ void cvt8(const float4 v0, const float4 v1,
                                     uint4 &hi, uint4 &lo) {
    float f[8] = {v0.x, v0.y, v0.z, v0.w, v1.x, v1.y, v1.z, v1.w};
    float h[8], l[8];
#pragma unroll
    for (int i = 0; i < 8; ++i) {
        h[i] = __bfloat162float(__float2bfloat16(f[i]));
        l[i] = f[i] - h[i];
    }
    hi.x = pkbf(h[0], h[1]); hi.y = pkbf(h[2], h[3]);
    hi.z = pkbf(h[4], h[5]); hi.w = pkbf(h[6], h[7]);
    lo.x = pkbf(l[0], l[1]); lo.y = pkbf(l[2], l[3]);
    lo.z = pkbf(l[4], l[5]); lo.w = pkbf(l[6], l[7]);
}

// ---------------- HMMA (mma.sync) 16x8x16 bf16 -------------------------------
__device__ __forceinline__ void mma16816(float* d, uint32_t a0, uint32_t a1,
                                         uint32_t a2, uint32_t a3,
                                         uint32_t b0, uint32_t b1) {
    asm volatile(
        "mma.sync.aligned.m16n8k16.row.col.f32.bf16.bf16.f32 "
        "{%0,%1,%2,%3},{%4,%5,%6,%7},{%8,%9},{%0,%1,%2,%3};"
        : "+f"(d[0]), "+f"(d[1]), "+f"(d[2]), "+f"(d[3])
        : "r"(a0), "r"(a1), "r"(a2), "r"(a3), "r"(b0), "r"(b1));
}

// ---------------- decoder GEMM via mma.sync (3-term bf16 compensation) -------
__global__ void __launch_bounds__(256, 1) k_mma(
    const float* __restrict__ X, const float* __restrict__ W,
    const float* __restrict__ bias, float* __restrict__ out, int ldc) {
    __shared__ __align__(16) char sm[40960];
    const int tid = threadIdx.x;
    const int wid = tid >> 5, lid = tid & 31;
    const int m0 = blockIdx.x * 128;
    const int n0 = blockIdx.y * 128;
    const int warpM = wid >> 2;
    const int warpN = wid & 3;
    const int laneR = lid >> 2;
    const int laneC2 = (lid & 3) * 2;

    const int lrow = tid >> 1;
    const int lseg = tid & 1;
    const float* arow = X + (size_t)(m0 + lrow) * 1024 + lseg * 16;
    const float* brow = W + (size_t)(n0 + lrow) * 1024 + lseg * 16;
    const int sst = lrow * 80 + lseg * 32;

    float acc[4][4][4];
#pragma unroll
    for (int a = 0; a < 4; ++a)
#pragma unroll
        for (int b = 0; b < 4; ++b)
#pragma unroll
            for (int c = 0; c < 4; ++c) acc[a][b][c] = 0.f;

    float4 ra[4], rb[4];
#pragma unroll
    for (int i = 0; i < 4; ++i) {
        ra[i] = *(const float4*)(arow + i * 4);
        rb[i] = *(const float4*)(brow + i * 4);
    }

    const int NCH = 1024 / 32;
    for (int kc = 0; kc < NCH; ++kc) {
        {
            uint4 h0, l0, h1, l1;
            cvt8(ra[0], ra[1], h0, l0);
            cvt8(ra[2], ra[3], h1, l1);
            *(uint4*)(sm + sst) = h0;
            *(uint4*)(sm + sst + 16) = h1;
            *(uint4*)(sm + 10240 + sst) = l0;
            *(uint4*)(sm + 10240 + sst + 16) = l1;
            cvt8(rb[0], rb[1], h0, l0);
            cvt8(rb[2], rb[3], h1, l1);
            *(uint4*)(sm + 20480 + sst) = h0;
            *(uint4*)(sm + 20480 + sst + 16) = h1;
            *(uint4*)(sm + 30720 + sst) = l0;
            *(uint4*)(sm + 30720 + sst + 16) = l1;
        }
        __syncthreads();
        if (kc + 1 < NCH) {
            const float* an = arow + (kc + 1) * 32;
            const float* bn = brow + (kc + 1) * 32;
#pragma unroll
            for (int i = 0; i < 4; ++i) {
                ra[i] = *(const float4*)(an + i * 4);
                rb[i] = *(const float4*)(bn + i * 4);
            }
        }
#pragma unroll
        for (int ks = 0; ks < 2; ++ks) {
            uint32_t ah[4][4], al[4][4], bh[4][2], bl[4][2];
#pragma unroll
            for (int mt = 0; mt < 4; ++mt) {
                int hb = (warpM * 64 + mt * 16 + laneR) * 40 + ks * 16 + laneC2;
                const char* pA = sm + hb * 2;
#pragma unroll
                for (int q = 0; q < 4; ++q) {
                    int off = ((q & 1) ? 8 * 80 : 0) + ((q & 2) ? 16 : 0);
                    ah[mt][q] = *(const uint32_t*)(pA + off);
                    al[mt][q] = *(const uint32_t*)(pA + 10240 + off);
                }
            }
#pragma unroll
            for (int nt = 0; nt < 4; ++nt) {
                int hb = (warpN * 32 + nt * 8 + laneR) * 40 + ks * 16 + laneC2;
                const char* pB = sm + 20480 + hb * 2;
                bh[nt][0] = *(const uint32_t*)(pB);
                bh[nt][1] = *(const uint32_t*)(pB + 16);
                bl[nt][0] = *(const uint32_t*)(pB + 10240);
                bl[nt][1] = *(const uint32_t*)(pB + 10240 + 16);
            }
#pragma unroll
            for (int mt = 0; mt < 4; ++mt)
#pragma unroll
                for (int nt = 0; nt < 4; ++nt)
                    mma16816(acc[mt][nt], ah[mt][0], ah[mt][1], ah[mt][2], ah[mt][3],
                             bh[nt][0], bh[nt][1]);
#pragma unroll
            for (int mt = 0; mt < 4; ++mt)
#pragma unroll
                for (int nt = 0; nt < 4; ++nt)
                    mma16816(acc[mt][nt], ah[mt][0], ah[mt][1], ah[mt][2], ah[mt][3],
                             bl[nt][0], bl[nt][1]);
#pragma unroll
            for (int mt = 0; mt < 4; ++mt)
#pragma unroll
                for (int nt = 0; nt < 4; ++nt)
                    mma16816(acc[mt][nt], al[mt][0], al[mt][1], al[mt][2], al[mt][3],
                             bh[nt][0], bh[nt][1]);
        }
        __syncthreads();
    }

#pragma unroll
    for (int mt = 0; mt < 4; ++mt) {
        int m = m0 + warpM * 64 + mt * 16 + laneR;
#pragma unroll
        for (int nt = 0; nt < 4; ++nt) {
            int n = n0 + warpN * 32 + nt * 8 + laneC2;
            float bx = bias[n], by = bias[n + 1];
            *(float2*)(out + (size_t)m * ldc + n) =
                make_float2(acc[mt][nt][0] + bx, acc[mt][nt][1] + by);
            *(float2*)(out + (size_t)(m + 8) * ldc + n) =
                make_float2(acc[mt][nt][2] + bx, acc[mt][nt][3] + by);
        }
    }
}

// ---------------- xg precompute GEMM (exact fp32, f32x2) ---------------------
__global__ void __launch_bounds__(256, 2) k_gemm_xg(
    const float* __restrict__ X, const float* __restrict__ Wd,
    float* __restrict__ out) {
    __shared__ __align__(16) float sa[16][132];
    __shared__ __align__(16) float sb[16][132];
    const int m0 = blockIdx.x * 128;
    const int n0 = blockIdx.y * 128;
    const int tid = threadIdx.x;
    const int tn = tid & 15, tm = tid >> 4;
    unsigned long long acc[8][4];
#pragma unroll
    for (int i = 0; i < 8; i++)
#pragma unroll
        for (int p = 0; p < 4; p++) acc[i][p] = 0ULL;

    float4 pa[2], pb[2];
#pragma unroll
    for (int i = 0; i < 2; ++i) {
        int lid = tid + i * 256;
        int row = lid >> 2, kq = lid & 3;
        pa[i] = *(const float4*)(X + (size_t)(m0 + row) * NHID + kq * 4);
        pb[i] = *(const float4*)(Wd + (size_t)(n0 + row) * NHID + kq * 4);
    }
    for (int k0 = 0; k0 < NHID; k0 += 16) {
#pragma unroll
        for (int i = 0; i < 2; ++i) {
            int lid = tid + i * 256;
            int row = lid >> 2, kq = lid & 3;
            sa[kq * 4 + 0][row] = pa[i].x; sa[kq * 4 + 1][row] = pa[i].y;
            sa[kq * 4 + 2][row] = pa[i].z; sa[kq * 4 + 3][row] = pa[i].w;
            sb[kq * 4 + 0][row] = pb[i].x; sb[kq * 4 + 1][row] = pb[i].y;
            sb[kq * 4 + 2][row] = pb[i].z; sb[kq * 4 + 3][row] = pb[i].w;
        }
        __syncthreads();
        if (k0 + 16 < NHID) {
#pragma unroll
            for (int i = 0; i < 2; ++i) {
                int lid = tid + i * 256;
                int row = lid >> 2, kq = lid & 3;
                pa[i] = *(const float4*)(X + (size_t)(m0 + row) * NHID + (k0 + 16) + kq * 4);
                pb[i] = *(const float4*)(Wd + (size_t)(n0 + row) * NHID + (k0 + 16) + kq * 4);
            }
        }
#pragma unroll
        for (int k = 0; k < 16; ++k) {
            unsigned long long b2[4];
#pragma unroll
            for (int p = 0; p < 4; ++p)
                b2[p] = *(const unsigned long long*)&sb[k][p * 32 + tn * 2];
#pragma unroll
            for (int i = 0; i < 8; ++i) {
                unsigned long long as = splat2(sa[k][tm * 8 + i]);
#pragma unroll
                for (int p = 0; p < 4; ++p) ffma2(acc[i][p], as, b2[p]);
            }
        }
        __syncthreads();
    }
#pragma unroll
    for (int i = 0; i < 8; ++i) {
        int m = m0 + tm * 8 + i;
#pragma unroll
        for (int p = 0; p < 4; ++p) {
            int nn = n0 + p * 32 + tn * 2;
            float2 v = unpk(acc[i][p]);
            *(float2*)(out + (size_t)m * (NB * 4 * BS) + nn) = v;
        }
    }
}

// ---------------- embedding gather ------------------------------------------
__global__ void k_embed(const int* __restrict__ tokens, const float* __restrict__ embW,
                        float* __restrict__ x) {
    int tb = blockIdx.x;
    int tok = tokens[tb];
    const float4* src = (const float4*)(embW + (size_t)tok * NINP);
    float4* dst = (float4*)(x + (size_t)tb * NINP);
    dst[threadIdx.x] = src[threadIdx.x];
}

// ---------------- persistent recurrence kernel (one layer) -------------------
// grid: 128 CTAs x 256 threads (all co-resident on 148 SMs).
// CTA r: gate block n = r&3, j-tile j0 = (r>>2)*8. Whh slice lives in smem;
// c state lives in registers for the whole layer.
__global__ void __launch_bounds__(256, 1) k_rec(
    const float* __restrict__ xg,     // [T][B][4096]
    const float* __restrict__ Whh_l,  // [NB][4BS][BS]
    const float* __restrict__ bih_l, const float* __restrict__ bhh_l,
    const float* __restrict__ h0_l, const float* __restrict__ c0_l,
    const float* __restrict__ wq, const float* __restrict__ bq,
    const float* __restrict__ wk, const float* __restrict__ bk,
    const float* __restrict__ wv, const float* __restrict__ bv,
    const float* __restrict__ wfc, const float* __restrict__ bfc,
    const float* __restrict__ lng, const float* __restrict__ lnb,
    float* __restrict__ hbuf, float* __restrict__ hlbuf,
    float* __restrict__ ys,           // [T][B][NHID]
    float* __restrict__ outH, float* __restrict__ outC) {
    __shared__ __align__(16) float swf[256 * 34];   // W slice [k][col], 34 KB
    __shared__ __align__(16) float sa_s[2112];       // gates h-tile / mha sh alias
    __shared__ float sq[DK], skk[NB][DK], svv[NB][DK], ssc[NB], sp[NB], so[DK];
    __shared__ float sred[8];

    const int tid = threadIdx.x;
    const int r = blockIdx.x;
    const int n = r & 3;
    const int j0 = (r >> 2) * 8;
    const int tj = tid & 7, tb2 = tid >> 3;
    const int j = j0 + tj;

    // ---- load Whh slice into smem once (coalesced along k) ----
    const float* W = Whh_l + (size_t)n * 4 * BS * BS;
#pragma unroll
    for (int e = 0; e < 8; ++e) {
        int idx = e * 256 + tid;        // 0..2047
        int col = idx >> 6;             // 0..31
        int kq = idx & 63;              // k/4
        int g = col & 3, jj = col >> 2;
        float4 v = *(const float4*)(W + (size_t)(g * BS + j0 + jj) * BS + kq * 4);
        swf[(kq * 4 + 0) * 34 + col] = v.x;
        swf[(kq * 4 + 1) * 34 + col] = v.y;
        swf[(kq * 4 + 2) * 34 + col] = v.z;
        swf[(kq * 4 + 3) * 34 + col] = v.w;
    }

    // ---- biases, c registers ----
    const float b_i = bih_l[n * 4 * BS + 0 * BS + j] + bhh_l[n * 4 * BS + 0 * BS + j];
    const float b_f = bih_l[n * 4 * BS + 1 * BS + j] + bhh_l[n * 4 * BS + 1 * BS + j];
    const float b_g = bih_l[n * 4 * BS + 2 * BS + j] + bhh_l[n * 4 * BS + 2 * BS + j];
    const float b_o = bih_l[n * 4 * BS + 3 * BS + j] + bhh_l[n * 4 * BS + 3 * BS + j];
    float creg[2];
#pragma unroll
    for (int bi = 0; bi < 2; ++bi) {
        int bb = tb2 * 2 + bi;
        creg[bi] = c0_l[bb * NHID + n * BS + j];
    }

    // ---- h0 -> hbuf (cooperative) ----
    {
        int base = (r * 256 + tid) * 2;
        float2 v = *(const float2*)(h0_l + base);
        __stcg((float2*)(hbuf + base), v);
    }
    grid_bar();

    for (int t = 0; t < T; ++t) {
        // ===== gates phase =====
        const float* xg_t = xg + (size_t)t * B * (NB * 4 * BS);
        unsigned long long acc[2][2];
#pragma unroll
        for (int bi = 0; bi < 2; ++bi) {
            int bb = tb2 * 2 + bi;
            const float* xr = xg_t + (size_t)bb * (NB * 4 * BS) + n * 4 * BS + j;
            acc[bi][0] = pack2(__ldg(xr) + b_i, __ldg(xr + BS) + b_f);
            acc[bi][1] = pack2(__ldg(xr + 2 * BS) + b_g, __ldg(xr + 3 * BS) + b_o);
        }
        const float* A = hbuf + n * BS;
        float4 pa[2];
#pragma unroll
        for (int i = 0; i < 2; ++i) {
            int lid = tid + i * 256;
            int bb = lid >> 3, kq = lid & 7;
            pa[i] = __ldcg((const float4*)(A + (size_t)bb * NHID + kq * 4));
        }
        for (int k0 = 0; k0 < BS; k0 += 32) {
            __syncthreads();
#pragma unroll
            for (int i = 0; i < 2; ++i) {
                int lid = tid + i * 256;
                int bb = lid >> 3, kq = lid & 7;
                sa_s[(kq * 4 + 0) * 65 + bb] = pa[i].x;
                sa_s[(kq * 4 + 1) * 65 + bb] = pa[i].y;
                sa_s[(kq * 4 + 2) * 65 + bb] = pa[i].z;
                sa_s[(kq * 4 + 3) * 65 + bb] = pa[i].w;
            }
            __syncthreads();
            if (k0 + 32 < BS) {
#pragma unroll
                for (int i = 0; i < 2; ++i) {
                    int lid = tid + i * 256;
                    int bb = lid >> 3, kq = lid & 7;
                    pa[i] = __ldcg((const float4*)(A + (size_t)bb * NHID + k0 + 32 + kq * 4));
                }
            }
#pragma unroll
            for (int k = 0; k < 32; ++k) {
                unsigned long long w01 = *(const unsigned long long*)&swf[(k0 + k) * 34 + tj * 4];
                unsigned long long w23 = *(const unsigned long long*)&swf[(k0 + k) * 34 + tj * 4 + 2];
#pragma unroll
                for (int bi = 0; bi < 2; ++bi) {
                    unsigned long long as = splat2(sa_s[k * 65 + tb2 * 2 + bi]);
                    ffma2(acc[bi][0], as, w01);
                    ffma2(acc[bi][1], as, w23);
                }
            }
        }
        // LSTM cell epilogue
#pragma unroll
        for (int bi = 0; bi < 2; ++bi) {
            int bb = tb2 * 2 + bi;
            float2 g01 = unpk(acc[bi][0]);
            float2 g23 = unpk(acc[bi][1]);
            float cn = sigmoidf_(g01.y) * creg[bi] + sigmoidf_(g01.x) * tanhf(g23.x);
            creg[bi] = cn;
            __stcg(hlbuf + bb * NHID + n * BS + j, sigmoidf_(g23.y) * tanhf(cn));
        }
        grid_bar();

        // ===== MHA phase: this CTA handles items r and r+128 =====
        float* ys_t = ys + (size_t)t * B * NHID;
        float* sh = sa_s;  // [4][256] alias
#pragma unroll
        for (int it2 = 0; it2 < 2; ++it2) {
            int item = r + it2 * 128;
            int nn = item >> 6, bb = item & 63;
#pragma unroll
            for (int i = 0; i < 4; ++i) {
                int idx = tid + i * 256;
                sh[idx] = __ldcg(hlbuf + (size_t)bb * NHID + idx);
            }
            __syncthreads();
            if (tid < 144) {
                const float *wp, *bp, *hv; float* dst; int d;
                if (tid < 16) { d = tid; wp = wq; bp = bq; hv = sh + nn * BS; dst = &sq[d]; }
                else if (tid < 80) { int m = (tid - 16) >> 4; d = (tid - 16) & 15;
                                     wp = wk; bp = bk; hv = sh + m * BS; dst = &skk[m][d]; }
                else { int m = (tid - 80) >> 4; d = (tid - 80) & 15;
                       wp = wv; bp = bv; hv = sh + m * BS; dst = &svv[m][d]; }
                const float* w = wp + d * BS;
                float a0 = 0, a1 = 0, a2 = 0, a3 = 0;
#pragma unroll 8
                for (int jj = 0; jj < BS; jj += 4) {
                    a0 += hv[jj] * w[jj];         a1 += hv[jj + 1] * w[jj + 1];
                    a2 += hv[jj + 2] * w[jj + 2]; a3 += hv[jj + 3] * w[jj + 3];
                }
                *dst = a0 + a1 + a2 + a3 + bp[d];
            }
            __syncthreads();
            if (tid < 4) {
                float s = 0;
#pragma unroll
                for (int d = 0; d < DK; ++d) s += sq[d] * skk[tid][d];
                ssc[tid] = s * 0.25f;
            }
            __syncthreads();
            if (tid < 4) {
                float mx = fmaxf(fmaxf(ssc[0], ssc[1]), fmaxf(ssc[2], ssc[3]));
                float sum = expf(ssc[0] - mx) + expf(ssc[1] - mx) +
                            expf(ssc[2] - mx) + expf(ssc[3] - mx);
                sp[tid] = expf(ssc[tid] - mx) / sum;
            }
            __syncthreads();
            if (tid < DK) {
                float o = 0;
#pragma unroll
                for (int m = 0; m < NB; ++m) o += sp[m] * svv[m][tid];
                so[tid] = o;
            }
            __syncthreads();
            float val = bfc[tid] + sh[nn * BS + tid];
#pragma unroll
            for (int d = 0; d < DK; ++d) val += so[d] * wfc[tid * DK + d];
            float s = val;
#pragma unroll
            for (int off = 16; off; off >>= 1) s += __shfl_down_sync(0xffffffffu, s, off);
            if ((tid & 31) == 0) sred[tid >> 5] = s;
            __syncthreads();
            float mu = 0;
#pragma unroll
            for (int i = 0; i < 8; ++i) mu += sred[i];
            mu *= (1.f / BS);
            __syncthreads();
            float dv = val - mu;
            float s2 = dv * dv;
#pragma unroll
            for (int off = 16; off; off >>= 1) s2 += __shfl_down_sync(0xffffffffu, s2, off);
            if ((tid & 31) == 0) sred[tid >> 5] = s2;
            __syncthreads();
            float var = 0;
#pragma unroll
            for (int i = 0; i < 8; ++i) var += sred[i];
            var *= (1.f / BS);
            float y = dv * rsqrtf(var + 1e-5f) * lng[tid] + lnb[tid];
            int idx = bb * NHID + nn * BS + tid;
            __stcg(hbuf + idx, y);
            ys_t[idx] = y;
            __syncthreads();
        }
        grid_bar();
    }

    // ---- final state writeout ----
    {
        int base = (r * 256 + tid) * 2;
        float2 v = __ldcg((const float2*)(hbuf + base));
        *(float2*)(outH + base) = v;
    }
#pragma unroll
    for (int bi = 0; bi < 2; ++bi) {
        int bb = tb2 * 2 + bi;
        outC[bb * NHID + n * BS + j] = creg[bi];
    }
}

// ---------------- host driver ------------------------------------------------
extern "C" void kernel_launch(void* const* d_in, const int* in_sizes, int n_in,
                              void* d_out, int out_size) {
    const int* tokens = (const int*)d_in[0];
    const float* h0 = (const float*)d_in[1];
    const float* c0 = (const float*)d_in[2];
    const float* embW = (const float*)d_in[3];
    const float* Wih = (const float*)d_in[4];
    const float* Whh = (const float*)d_in[5];
    const float* bih = (const float*)d_in[6];
    const float* bhh = (const float*)d_in[7];
    const float* wq = (const float*)d_in[8];
    const float* bq = (const float*)d_in[9];
    const float* wk = (const float*)d_in[10];
    const float* bk = (const float*)d_in[11];
    const float* wv = (const float*)d_in[12];
    const float* bv = (const float*)d_in[13];
    const float* wfc = (const float*)d_in[14];
    const float* bfc = (const float*)d_in[15];
    const float* lng = (const float*)d_in[16];
    const float* lnb = (const float*)d_in[17];
    const float* Wd = (const float*)d_in[18];
    const float* bd = (const float*)d_in[19];
    float* out = (float*)d_out;

    float *xb, *xg, *hbuf, *hlbuf;
    cudaGetSymbolAddress((void**)&xb, g_xbuf);
    cudaGetSymbolAddress((void**)&xg, g_xg);
    cudaGetSymbolAddress((void**)&hbuf, g_h);
    cudaGetSymbolAddress((void**)&hlbuf, g_hl);
    float* x0 = xb;
    float* x1 = xb + (size_t)T * B * NHID;

    k_embed<<<T * B, 256>>>(tokens, embW, x0);

    const size_t DECN = (size_t)T * B * NTOK;
    for (int l = 0; l < NLAYERS; ++l) {
        const float* xin = (l == 0) ? x0 : x1;
        float* xout = (l == 0) ? x1 : x0;
        const float* Wih_l = Wih + (size_t)l * NB * 4 * BS * NINP;
        const float* Whh_l = Whh + (size_t)l * NB * 4 * BS * BS;
        const float* bih_l = bih + (size_t)l * NB * 4 * BS;
        const float* bhh_l = bhh + (size_t)l * NB * 4 * BS;
        // hoisted input-gates GEMM (exact fp32): xg = xin @ Wih_l^T
        k_gemm_xg<<<dim3(32, 32), 256>>>(xin, Wih_l, xg);
        // persistent fused recurrence for this layer
        k_rec<<<NCTA, 256>>>(xg, Whh_l, bih_l, bhh_l,
                             h0 + (size_t)l * B * NHID, c0 + (size_t)l * B * NHID,
                             wq, bq, wk, bk, wv, bv, wfc, bfc, lng, lnb,
                             hbuf, hlbuf, xout,
                             out + DECN + (size_t)l * B * NHID,
                             out + DECN + (size_t)NLAYERS * B * NHID +
                                 (size_t)l * B * NHID);
    }
    // decoder on tensor cores (3-term bf16): out = x0 @ Wd^T + bd
    k_mma<<<dim3(32, 250), 256>>>(x0, Wd, bd, out, NTOK);
}

// round 7
// speedup vs baseline: 1.1961x; 1.1961x over previous
#include <cuda_runtime.h>
#include <cuda_bf16.h>
#include <cstdint>

#define NLAYERS 2
#define NB 4
#define BS 256
#define NHID 1024
#define NINP 1024
#define NTOK 32000
#define T 64
#define B 64
#define DK 16
#define NCTA 128

// ---------------- scratch (device globals: no allocation allowed) ----------
__device__ float g_xbuf[2][(size_t)T * B * NHID];
__device__ float g_xg[(size_t)T * B * NB * 4 * BS];
__device__ float g_h[B * NHID];
__device__ float g_hl[B * NHID];
__device__ unsigned g_flags[NCTA];   // monotonic per-CTA barrier flags

// ---------------- f32x2 helpers ---------------------------------------------
__device__ __forceinline__ unsigned long long splat2(float a) {
    unsigned long long r;
    unsigned int u = __float_as_uint(a);
    asm("mov.b64 %0, {%1, %1};" : "=l"(r) : "r"(u));
    return r;
}
__device__ __forceinline__ unsigned long long pack2(float x, float y) {
    unsigned long long r;
    asm("mov.b64 %0, {%1, %2};" : "=l"(r)
        : "r"(__float_as_uint(x)), "r"(__float_as_uint(y)));
    return r;
}
__device__ __forceinline__ void ffma2(unsigned long long &c, unsigned long long a,
                                      unsigned long long b) {
    asm("fma.rn.f32x2 %0, %1, %2, %0;" : "+l"(c) : "l"(a), "l"(b));
}
__device__ __forceinline__ float2 unpk(unsigned long long v) {
    unsigned int x, y;
    asm("mov.b64 {%0, %1}, %2;" : "=r"(x), "=r"(y) : "l"(v));
    return make_float2(__uint_as_float(x), __uint_as_float(y));
}
__device__ __forceinline__ float sigmoidf_(float x) { return 1.f / (1.f + expf(-x)); }

// ---------------- bf16 split helpers ----------------------------------------
__device__ __forceinline__ uint32_t pkbf(float a, float b) {
    __nv_bfloat162 t = __floats2bfloat162_rn(a, b);
    return *reinterpret_cast<uint32_t*>(&t);
}
__device__ __forceinline__ void cvt8(const float4 v0, const float4 v1,
                                     uint4 &hi, uint4 &lo) {
    float f[8] = {v0.x, v0.y, v0.z, v0.w, v1.x, v1.y, v1.z, v1.w};
    float h[8], l[8];
#pragma unroll
    for (int i = 0; i < 8; ++i) {
        h[i] = __bfloat162float(__float2bfloat16(f[i]));
        l[i] = f[i] - h[i];
    }
    hi.x = pkbf(h[0], h[1]); hi.y = pkbf(h[2], h[3]);
    hi.z = pkbf(h[4], h[5]); hi.w = pkbf(h[6], h[7]);
    lo.x = pkbf(l[0], l[1]); lo.y = pkbf(l[2], l[3]);
    lo.z = pkbf(l[4], l[5]); lo.w = pkbf(l[6], l[7]);
}

// ---------------- HMMA (mma.sync) 16x8x16 bf16 -------------------------------
__device__ __forceinline__ void mma16816(float* d, uint32_t a0, uint32_t a1,
                                         uint32_t a2, uint32_t a3,
                                         uint32_t b0, uint32_t b1) {
    asm volatile(
        "mma.sync.aligned.m16n8k16.row.col.f32.bf16.bf16.f32 "
        "{%0,%1,%2,%3},{%4,%5,%6,%7},{%8,%9},{%0,%1,%2,%3};"
        : "+f"(d[0]), "+f"(d[1]), "+f"(d[2]), "+f"(d[3])
        : "r"(a0), "r"(a1), "r"(a2), "r"(a3), "r"(b0), "r"(b1));
}

// ---------------- decoder GEMM via mma.sync (3-term bf16 compensation) -------
__global__ void __launch_bounds__(256, 1) k_mma(
    const float* __restrict__ X, const float* __restrict__ W,
    const float* __restrict__ bias, float* __restrict__ out, int ldc) {
    __shared__ __align__(16) char sm[40960];
    const int tid = threadIdx.x;
    const int wid = tid >> 5, lid = tid & 31;
    const int m0 = blockIdx.x * 128;
    const int n0 = blockIdx.y * 128;
    const int warpM = wid >> 2;
    const int warpN = wid & 3;
    const int laneR = lid >> 2;
    const int laneC2 = (lid & 3) * 2;

    const int lrow = tid >> 1;
    const int lseg = tid & 1;
    const float* arow = X + (size_t)(m0 + lrow) * 1024 + lseg * 16;
    const float* brow = W + (size_t)(n0 + lrow) * 1024 + lseg * 16;
    const int sst = lrow * 80 + lseg * 32;

    float acc[4][4][4];
#pragma unroll
    for (int a = 0; a < 4; ++a)
#pragma unroll
        for (int b = 0; b < 4; ++b)
#pragma unroll
            for (int c = 0; c < 4; ++c) acc[a][b][c] = 0.f;

    float4 ra[4], rb[4];
#pragma unroll
    for (int i = 0; i < 4; ++i) {
        ra[i] = *(const float4*)(arow + i * 4);
        rb[i] = *(const float4*)(brow + i * 4);
    }

    const int NCH = 1024 / 32;
    for (int kc = 0; kc < NCH; ++kc) {
        {
            uint4 h0, l0, h1, l1;
            cvt8(ra[0], ra[1], h0, l0);
            cvt8(ra[2], ra[3], h1, l1);
            *(uint4*)(sm + sst) = h0;
            *(uint4*)(sm + sst + 16) = h1;
            *(uint4*)(sm + 10240 + sst) = l0;
            *(uint4*)(sm + 10240 + sst + 16) = l1;
            cvt8(rb[0], rb[1], h0, l0);
            cvt8(rb[2], rb[3], h1, l1);
            *(uint4*)(sm + 20480 + sst) = h0;
            *(uint4*)(sm + 20480 + sst + 16) = h1;
            *(uint4*)(sm + 30720 + sst) = l0;
            *(uint4*)(sm + 30720 + sst + 16) = l1;
        }
        __syncthreads();
        if (kc + 1 < NCH) {
            const float* an = arow + (kc + 1) * 32;
            const float* bn = brow + (kc + 1) * 32;
#pragma unroll
            for (int i = 0; i < 4; ++i) {
                ra[i] = *(const float4*)(an + i * 4);
                rb[i] = *(const float4*)(bn + i * 4);
            }
        }
#pragma unroll
        for (int ks = 0; ks < 2; ++ks) {
            uint32_t ah[4][4], al[4][4], bh[4][2], bl[4][2];
#pragma unroll
            for (int mt = 0; mt < 4; ++mt) {
                int hb = (warpM * 64 + mt * 16 + laneR) * 40 + ks * 16 + laneC2;
                const char* pA = sm + hb * 2;
#pragma unroll
                for (int q = 0; q < 4; ++q) {
                    int off = ((q & 1) ? 8 * 80 : 0) + ((q & 2) ? 16 : 0);
                    ah[mt][q] = *(const uint32_t*)(pA + off);
                    al[mt][q] = *(const uint32_t*)(pA + 10240 + off);
                }
            }
#pragma unroll
            for (int nt = 0; nt < 4; ++nt) {
                int hb = (warpN * 32 + nt * 8 + laneR) * 40 + ks * 16 + laneC2;
                const char* pB = sm + 20480 + hb * 2;
                bh[nt][0] = *(const uint32_t*)(pB);
                bh[nt][1] = *(const uint32_t*)(pB + 16);
                bl[nt][0] = *(const uint32_t*)(pB + 10240);
                bl[nt][1] = *(const uint32_t*)(pB + 10240 + 16);
            }
#pragma unroll
            for (int mt = 0; mt < 4; ++mt)
#pragma unroll
                for (int nt = 0; nt < 4; ++nt)
                    mma16816(acc[mt][nt], ah[mt][0], ah[mt][1], ah[mt][2], ah[mt][3],
                             bh[nt][0], bh[nt][1]);
#pragma unroll
            for (int mt = 0; mt < 4; ++mt)
#pragma unroll
                for (int nt = 0; nt < 4; ++nt)
                    mma16816(acc[mt][nt], ah[mt][0], ah[mt][1], ah[mt][2], ah[mt][3],
                             bl[nt][0], bl[nt][1]);
#pragma unroll
            for (int mt = 0; mt < 4; ++mt)
#pragma unroll
                for (int nt = 0; nt < 4; ++nt)
                    mma16816(acc[mt][nt], al[mt][0], al[mt][1], al[mt][2], al[mt][3],
                             bh[nt][0], bh[nt][1]);
        }
        __syncthreads();
    }

#pragma unroll
    for (int mt = 0; mt < 4; ++mt) {
        int m = m0 + warpM * 64 + mt * 16 + laneR;
#pragma unroll
        for (int nt = 0; nt < 4; ++nt) {
            int n = n0 + warpN * 32 + nt * 8 + laneC2;
            float bx = bias[n], by = bias[n + 1];
            *(float2*)(out + (size_t)m * ldc + n) =
                make_float2(acc[mt][nt][0] + bx, acc[mt][nt][1] + by);
            *(float2*)(out + (size_t)(m + 8) * ldc + n) =
                make_float2(acc[mt][nt][2] + bx, acc[mt][nt][3] + by);
        }
    }
}

// ---------------- xg precompute GEMM (exact fp32, f32x2) ---------------------
__global__ void __launch_bounds__(256, 2) k_gemm_xg(
    const float* __restrict__ X, const float* __restrict__ Wd,
    float* __restrict__ out) {
    __shared__ __align__(16) float sa[16][132];
    __shared__ __align__(16) float sb[16][132];
    const int m0 = blockIdx.x * 128;
    const int n0 = blockIdx.y * 128;
    const int tid = threadIdx.x;
    const int tn = tid & 15, tm = tid >> 4;
    unsigned long long acc[8][4];
#pragma unroll
    for (int i = 0; i < 8; i++)
#pragma unroll
        for (int p = 0; p < 4; p++) acc[i][p] = 0ULL;

    float4 pa[2], pb[2];
#pragma unroll
    for (int i = 0; i < 2; ++i) {
        int lid = tid + i * 256;
        int row = lid >> 2, kq = lid & 3;
        pa[i] = *(const float4*)(X + (size_t)(m0 + row) * NHID + kq * 4);
        pb[i] = *(const float4*)(Wd + (size_t)(n0 + row) * NHID + kq * 4);
    }
    for (int k0 = 0; k0 < NHID; k0 += 16) {
#pragma unroll
        for (int i = 0; i < 2; ++i) {
            int lid = tid + i * 256;
            int row = lid >> 2, kq = lid & 3;
            sa[kq * 4 + 0][row] = pa[i].x; sa[kq * 4 + 1][row] = pa[i].y;
            sa[kq * 4 + 2][row] = pa[i].z; sa[kq * 4 + 3][row] = pa[i].w;
            sb[kq * 4 + 0][row] = pb[i].x; sb[kq * 4 + 1][row] = pb[i].y;
            sb[kq * 4 + 2][row] = pb[i].z; sb[kq * 4 + 3][row] = pb[i].w;
        }
        __syncthreads();
        if (k0 + 16 < NHID) {
#pragma unroll
            for (int i = 0; i < 2; ++i) {
                int lid = tid + i * 256;
                int row = lid >> 2, kq = lid & 3;
                pa[i] = *(const float4*)(X + (size_t)(m0 + row) * NHID + (k0 + 16) + kq * 4);
                pb[i] = *(const float4*)(Wd + (size_t)(n0 + row) * NHID + (k0 + 16) + kq * 4);
            }
        }
#pragma unroll
        for (int k = 0; k < 16; ++k) {
            unsigned long long b2[4];
#pragma unroll
            for (int p = 0; p < 4; ++p)
                b2[p] = *(const unsigned long long*)&sb[k][p * 32 + tn * 2];
#pragma unroll
            for (int i = 0; i < 8; ++i) {
                unsigned long long as = splat2(sa[k][tm * 8 + i]);
#pragma unroll
                for (int p = 0; p < 4; ++p) ffma2(acc[i][p], as, b2[p]);
            }
        }
        __syncthreads();
    }
#pragma unroll
    for (int i = 0; i < 8; ++i) {
        int m = m0 + tm * 8 + i;
#pragma unroll
        for (int p = 0; p < 4; ++p) {
            int nn = n0 + p * 32 + tn * 2;
            float2 v = unpk(acc[i][p]);
            *(float2*)(out + (size_t)m * (NB * 4 * BS) + nn) = v;
        }
    }
}

// ---------------- embedding gather ------------------------------------------
__global__ void k_embed(const int* __restrict__ tokens, const float* __restrict__ embW,
                        float* __restrict__ x) {
    int tb = blockIdx.x;
    int tok = tokens[tb];
    const float4* src = (const float4*)(embW + (size_t)tok * NINP);
    float4* dst = (float4*)(x + (size_t)tb * NINP);
    dst[threadIdx.x] = src[threadIdx.x];
}

// ---------------- flag-array grid barrier ------------------------------------
__device__ __forceinline__ void gbar(unsigned &gen) {
    __syncthreads();
    ++gen;
    if (threadIdx.x == 0) {
        __threadfence();
        *(volatile unsigned*)&g_flags[blockIdx.x] = gen;
    }
    if (threadIdx.x < NCTA) {
        while (*(volatile unsigned*)&g_flags[threadIdx.x] < gen) {}
    }
    __threadfence();
    __syncthreads();
}

// ---------------- persistent recurrence kernel v2 (one layer) ----------------
// grid 128 CTAs x 256 threads, ~170KB dynamic smem (1 CTA/SM, all co-resident).
#define SMEM_REC (42496 * 4)
__global__ void __launch_bounds__(256, 1) k_rec(
    const float* __restrict__ xg, const float* __restrict__ Whh_l,
    const float* __restrict__ bih_l, const float* __restrict__ bhh_l,
    const float* __restrict__ h0_l, const float* __restrict__ c0_l,
    const float* __restrict__ wq, const float* __restrict__ bq,
    const float* __restrict__ wk, const float* __restrict__ bk,
    const float* __restrict__ wv, const float* __restrict__ bv,
    const float* __restrict__ wfc, const float* __restrict__ bfc,
    const float* __restrict__ lng, const float* __restrict__ lnb,
    float* __restrict__ hbuf, float* __restrict__ hlbuf,
    float* __restrict__ ys,
    float* __restrict__ outH, float* __restrict__ outC) {
    extern __shared__ float smf[];
    float* swf  = smf;           // Whh slice [256 k][34 cols]  (8704 floats)
    float* sa2  = smf + 8704;    // h tile [64 bb][260]         (16640 floats; MHA aliases)
    float* smw  = smf + 25344;   // q/k/v weights [48][256]     (12288)
    float* swfc = smf + 37632;   // wfc [256][16]               (4096)
    float* sbfc = smf + 41728;   // 256
    float* slng = smf + 41984;   // 256
    float* slnb = smf + 42240;   // 256

    __shared__ float sq2[2][DK], skk2[2][NB][DK], svv2[2][NB][DK];
    __shared__ float ssc2[2][NB], sp2[2][NB], so2[2][DK], sredh[2][4];

    const int tid = threadIdx.x;
    const int r = blockIdx.x;
    const int n = r & 3;
    const int j0 = (r >> 2) * 8;
    const int tj = tid & 7, tb2 = tid >> 3;
    const int j = j0 + tj;
    const int lane = tid & 31;

    // ---- one-time preloads ----
    {
        const float* W = Whh_l + (size_t)n * 4 * BS * BS;
#pragma unroll
        for (int e = 0; e < 8; ++e) {
            int idx = e * 256 + tid;
            int col = idx >> 6, kq = idx & 63;
            int g = col & 3, jj = col >> 2;
            float4 v = *(const float4*)(W + (size_t)(g * BS + j0 + jj) * BS + kq * 4);
            swf[(kq * 4 + 0) * 34 + col] = v.x;
            swf[(kq * 4 + 1) * 34 + col] = v.y;
            swf[(kq * 4 + 2) * 34 + col] = v.z;
            swf[(kq * 4 + 3) * 34 + col] = v.w;
        }
#pragma unroll
        for (int i = 0; i < 4; ++i) {
            ((float4*)smw)[tid + i * 256] = ((const float4*)wq)[tid + i * 256];
            ((float4*)(smw + 4096))[tid + i * 256] = ((const float4*)wk)[tid + i * 256];
            ((float4*)(smw + 8192))[tid + i * 256] = ((const float4*)wv)[tid + i * 256];
            ((float4*)swfc)[tid + i * 256] = ((const float4*)wfc)[tid + i * 256];
        }
        sbfc[tid] = bfc[tid];
        slng[tid] = lng[tid];
        slnb[tid] = lnb[tid];
    }

    // biases + c registers
    const float b_i = bih_l[n * 4 * BS + 0 * BS + j] + bhh_l[n * 4 * BS + 0 * BS + j];
    const float b_f = bih_l[n * 4 * BS + 1 * BS + j] + bhh_l[n * 4 * BS + 1 * BS + j];
    const float b_g = bih_l[n * 4 * BS + 2 * BS + j] + bhh_l[n * 4 * BS + 2 * BS + j];
    const float b_o = bih_l[n * 4 * BS + 3 * BS + j] + bhh_l[n * 4 * BS + 3 * BS + j];
    float creg[2];
    creg[0] = c0_l[(tb2 * 2 + 0) * NHID + n * BS + j];
    creg[1] = c0_l[(tb2 * 2 + 1) * NHID + n * BS + j];

    unsigned bgen = g_flags[r];

    // h0 publish
    {
        int base = (r * 256 + tid) * 2;
        float2 v = *(const float2*)(h0_l + base);
        __stcg((float2*)(hbuf + base), v);
    }

    // xg prefetch for t=0
    float xgv[2][4];
    {
        const float* xg_t = xg;
#pragma unroll
        for (int bi = 0; bi < 2; ++bi) {
            const float* xr = xg_t + (size_t)(tb2 * 2 + bi) * 4096 + n * 1024 + j;
            xgv[bi][0] = __ldg(xr);       xgv[bi][1] = __ldg(xr + 256);
            xgv[bi][2] = __ldg(xr + 512); xgv[bi][3] = __ldg(xr + 768);
        }
    }
    gbar(bgen);

    // MHA half-CTA constants
    const int htid = tid & 127;
    const int half = tid >> 7;
    const int item = r + half * 128;
    const int nn2 = item >> 6;
    const int bb2 = item & 63;
    float* sh = sa2 + half * 1088;
#define HBAR() asm volatile("bar.sync %0, 128;" :: "r"(half + 1) : "memory")

    for (int t = 0; t < T; ++t) {
        // ===== gates phase =====
#pragma unroll 4
        for (int i = 0; i < 16; ++i) {
            int idx = tid + i * 256;
            int bb = idx >> 6, kq = idx & 63;
            float4 v = __ldcg((const float4*)(hbuf + (size_t)bb * NHID + n * BS) + kq);
            *(float4*)&sa2[bb * 260 + kq * 4] = v;
        }
        __syncthreads();

        unsigned long long a00 = pack2(xgv[0][0] + b_i, xgv[0][1] + b_f);
        unsigned long long a01 = pack2(xgv[0][2] + b_g, xgv[0][3] + b_o);
        unsigned long long a10 = pack2(xgv[1][0] + b_i, xgv[1][1] + b_f);
        unsigned long long a11 = pack2(xgv[1][2] + b_g, xgv[1][3] + b_o);
        const float* s0 = &sa2[(tb2 * 2 + 0) * 260];
        const float* s1 = &sa2[(tb2 * 2 + 1) * 260];
#pragma unroll 8
        for (int k = 0; k < 256; ++k) {
            unsigned long long w01 = *(const unsigned long long*)&swf[k * 34 + tj * 4];
            unsigned long long w23 = *(const unsigned long long*)&swf[k * 34 + tj * 4 + 2];
            unsigned long long as0 = splat2(s0[k]);
            unsigned long long as1 = splat2(s1[k]);
            ffma2(a00, as0, w01); ffma2(a01, as0, w23);
            ffma2(a10, as1, w01); ffma2(a11, as1, w23);
        }
        {
            float2 g01 = unpk(a00), g23 = unpk(a01);
            float cn = sigmoidf_(g01.y) * creg[0] + sigmoidf_(g01.x) * tanhf(g23.x);
            creg[0] = cn;
            __stcg(hlbuf + (tb2 * 2 + 0) * NHID + n * BS + j,
                   sigmoidf_(g23.y) * tanhf(cn));
            g01 = unpk(a10); g23 = unpk(a11);
            cn = sigmoidf_(g01.y) * creg[1] + sigmoidf_(g01.x) * tanhf(g23.x);
            creg[1] = cn;
            __stcg(hlbuf + (tb2 * 2 + 1) * NHID + n * BS + j,
                   sigmoidf_(g23.y) * tanhf(cn));
        }
        gbar(bgen);

        // ===== MHA phase (two items in parallel half-CTAs) =====
        float* ys_t = ys + (size_t)t * B * NHID;
        {
            const float4* src = (const float4*)(hlbuf + (size_t)bb2 * NHID);
            ((float4*)sh)[htid] = __ldcg(src + htid);
            ((float4*)sh)[htid + 128] = __ldcg(src + htid + 128);
        }
        HBAR();
        for (int w = htid; w < 144; w += 128) {
            const float *hv, *wrow; float* dst; float bpv;
            if (w < 16) { wrow = smw + w * 256; hv = sh + nn2 * 256;
                          dst = &sq2[half][w]; bpv = __ldg(bq + w); }
            else if (w < 80) { int m = (w - 16) >> 4, d = (w - 16) & 15;
                               wrow = smw + 4096 + d * 256; hv = sh + m * 256;
                               dst = &skk2[half][m][d]; bpv = __ldg(bk + d); }
            else { int m = (w - 80) >> 4, d = (w - 80) & 15;
                   wrow = smw + 8192 + d * 256; hv = sh + m * 256;
                   dst = &svv2[half][m][d]; bpv = __ldg(bv + d); }
            float a0 = 0, a1 = 0, a2 = 0, a3 = 0;
#pragma unroll 8
            for (int jj = 0; jj < 256; jj += 4) {
                a0 += hv[jj] * wrow[jj];         a1 += hv[jj + 1] * wrow[jj + 1];
                a2 += hv[jj + 2] * wrow[jj + 2]; a3 += hv[jj + 3] * wrow[jj + 3];
            }
            *dst = a0 + a1 + a2 + a3 + bpv;
        }
        HBAR();
        if (htid < 4) {
            float s = 0;
#pragma unroll
            for (int d = 0; d < DK; ++d) s += sq2[half][d] * skk2[half][htid][d];
            ssc2[half][htid] = s * 0.25f;
        }
        HBAR();
        if (htid < 4) {
            float mx = fmaxf(fmaxf(ssc2[half][0], ssc2[half][1]),
                             fmaxf(ssc2[half][2], ssc2[half][3]));
            float sum = expf(ssc2[half][0] - mx) + expf(ssc2[half][1] - mx) +
                        expf(ssc2[half][2] - mx) + expf(ssc2[half][3] - mx);
            sp2[half][htid] = expf(ssc2[half][htid] - mx) / sum;
        }
        HBAR();
        if (htid < DK) {
            float o = 0;
#pragma unroll
            for (int m = 0; m < NB; ++m) o += sp2[half][m] * svv2[half][m][htid];
            so2[half][htid] = o;
        }
        HBAR();
        float v0 = sbfc[htid] + sh[nn2 * 256 + htid];
        float v1 = sbfc[htid + 128] + sh[nn2 * 256 + htid + 128];
#pragma unroll
        for (int d = 0; d < DK; ++d) {
            v0 += so2[half][d] * swfc[htid * DK + d];
            v1 += so2[half][d] * swfc[(htid + 128) * DK + d];
        }
        float s = v0 + v1;
#pragma unroll
        for (int off = 16; off; off >>= 1) s += __shfl_down_sync(0xffffffffu, s, off);
        if (lane == 0) sredh[half][htid >> 5] = s;
        HBAR();
        float mu = (sredh[half][0] + sredh[half][1] + sredh[half][2] + sredh[half][3])
                   * (1.f / BS);
        HBAR();
        float dv0 = v0 - mu, dv1 = v1 - mu;
        float s2 = dv0 * dv0 + dv1 * dv1;
#pragma unroll
        for (int off = 16; off; off >>= 1) s2 += __shfl_down_sync(0xffffffffu, s2, off);
        if (lane == 0) sredh[half][htid >> 5] = s2;
        HBAR();
        float var = (sredh[half][0] + sredh[half][1] + sredh[half][2] + sredh[half][3])
                    * (1.f / BS);
        float rstd = rsqrtf(var + 1e-5f);
        float y0 = dv0 * rstd * slng[htid] + slnb[htid];
        float y1 = dv1 * rstd * slng[htid + 128] + slnb[htid + 128];
        int i0 = bb2 * NHID + nn2 * 256 + htid;
        __stcg(hbuf + i0, y0);       ys_t[i0] = y0;
        __stcg(hbuf + i0 + 128, y1); ys_t[i0 + 128] = y1;

        // prefetch xg for t+1 (independent of barrier)
        if (t + 1 < T) {
            const float* xg_t = xg + (size_t)(t + 1) * B * 4096;
#pragma unroll
            for (int bi = 0; bi < 2; ++bi) {
                const float* xr = xg_t + (size_t)(tb2 * 2 + bi) * 4096 + n * 1024 + j;
                xgv[bi][0] = __ldg(xr);       xgv[bi][1] = __ldg(xr + 256);
                xgv[bi][2] = __ldg(xr + 512); xgv[bi][3] = __ldg(xr + 768);
            }
        }
        gbar(bgen);
    }

    // final state writeout
    {
        int base = (r * 256 + tid) * 2;
        float2 v = __ldcg((const float2*)(hbuf + base));
        *(float2*)(outH + base) = v;
    }
    outC[(tb2 * 2 + 0) * NHID + n * BS + j] = creg[0];
    outC[(tb2 * 2 + 1) * NHID + n * BS + j] = creg[1];
#undef HBAR
}

// ---------------- host driver ------------------------------------------------
extern "C" void kernel_launch(void* const* d_in, const int* in_sizes, int n_in,
                              void* d_out, int out_size) {
    const int* tokens = (const int*)d_in[0];
    const float* h0 = (const float*)d_in[1];
    const float* c0 = (const float*)d_in[2];
    const float* embW = (const float*)d_in[3];
    const float* Wih = (const float*)d_in[4];
    const float* Whh = (const float*)d_in[5];
    const float* bih = (const float*)d_in[6];
    const float* bhh = (const float*)d_in[7];
    const float* wq = (const float*)d_in[8];
    const float* bq = (const float*)d_in[9];
    const float* wk = (const float*)d_in[10];
    const float* bk = (const float*)d_in[11];
    const float* wv = (const float*)d_in[12];
    const float* bv = (const float*)d_in[13];
    const float* wfc = (const float*)d_in[14];
    const float* bfc = (const float*)d_in[15];
    const float* lng = (const float*)d_in[16];
    const float* lnb = (const float*)d_in[17];
    const float* Wd = (const float*)d_in[18];
    const float* bd = (const float*)d_in[19];
    float* out = (float*)d_out;

    static int attr_set = 0;
    if (!attr_set) {
        cudaFuncSetAttribute(k_rec, cudaFuncAttributeMaxDynamicSharedMemorySize,
                             SMEM_REC);
        attr_set = 1;
    }

    float *xb, *xg, *hbuf, *hlbuf;
    cudaGetSymbolAddress((void**)&xb, g_xbuf);
    cudaGetSymbolAddress((void**)&xg, g_xg);
    cudaGetSymbolAddress((void**)&hbuf, g_h);
    cudaGetSymbolAddress((void**)&hlbuf, g_hl);
    float* x0 = xb;
    float* x1 = xb + (size_t)T * B * NHID;

    k_embed<<<T * B, 256>>>(tokens, embW, x0);

    const size_t DECN = (size_t)T * B * NTOK;
    for (int l = 0; l < NLAYERS; ++l) {
        const float* xin = (l == 0) ? x0 : x1;
        float* xout = (l == 0) ? x1 : x0;
        const float* Wih_l = Wih + (size_t)l * NB * 4 * BS * NINP;
        const float* Whh_l = Whh + (size_t)l * NB * 4 * BS * BS;
        const float* bih_l = bih + (size_t)l * NB * 4 * BS;
        const float* bhh_l = bhh + (size_t)l * NB * 4 * BS;
        k_gemm_xg<<<dim3(32, 32), 256>>>(xin, Wih_l, xg);
        k_rec<<<NCTA, 256, SMEM_REC>>>(xg, Whh_l, bih_l, bhh_l,
                                       h0 + (size_t)l * B * NHID,
                                       c0 + (size_t)l * B * NHID,
                                       wq, bq, wk, bk, wv, bv, wfc, bfc, lng, lnb,
                                       hbuf, hlbuf, xout,
                                       out + DECN + (size_t)l * B * NHID,
                                       out + DECN + (size_t)NLAYERS * B * NHID +
                                           (size_t)l * B * NHID);
    }
    k_mma<<<dim3(32, 250), 256>>>(x0, Wd, bd, out, NTOK);
}

// round 8
// speedup vs baseline: 1.4276x; 1.1936x over previous
#include <cuda_runtime.h>
#include <cuda_bf16.h>
#include <cstdint>

#define NLAYERS 2
#define NB 4
#define BS 256
#define NHID 1024
#define NINP 1024
#define NTOK 32000
#define T 64
#define B 64
#define DK 16
#define NCTA 128

// ---------------- scratch (device globals: no allocation allowed) ----------
__device__ float g_xbuf[2][(size_t)T * B * NHID];
__device__ float g_xg[(size_t)T * B * NB * 4 * BS];
__device__ float g_h[B * NHID];
__device__ float g_hl[B * NHID];
__device__ unsigned g_flags[NCTA * 32];   // one flag per 128B line

// ---------------- f32x2 helpers ---------------------------------------------
__device__ __forceinline__ unsigned long long splat2(float a) {
    unsigned long long r;
    unsigned int u = __float_as_uint(a);
    asm("mov.b64 %0, {%1, %1};" : "=l"(r) : "r"(u));
    return r;
}
__device__ __forceinline__ unsigned long long pack2(float x, float y) {
    unsigned long long r;
    asm("mov.b64 %0, {%1, %2};" : "=l"(r)
        : "r"(__float_as_uint(x)), "r"(__float_as_uint(y)));
    return r;
}
__device__ __forceinline__ void ffma2(unsigned long long &c, unsigned long long a,
                                      unsigned long long b) {
    asm("fma.rn.f32x2 %0, %1, %2, %0;" : "+l"(c) : "l"(a), "l"(b));
}
__device__ __forceinline__ float2 unpk(unsigned long long v) {
    unsigned int x, y;
    asm("mov.b64 {%0, %1}, %2;" : "=r"(x), "=r"(y) : "l"(v));
    return make_float2(__uint_as_float(x), __uint_as_float(y));
}
__device__ __forceinline__ float sigmoidf_(float x) { return 1.f / (1.f + expf(-x)); }

// ---------------- bf16 split helpers ----------------------------------------
__device__ __forceinline__ uint32_t pkbf(float a, float b) {
    __nv_bfloat162 t = __floats2bfloat162_rn(a, b);
    return *reinterpret_cast<uint32_t*>(&t);
}
__device__ __forceinline__ void cvt8(const float4 v0, const float4 v1,
                                     uint4 &hi, uint4 &lo) {
    float f[8] = {v0.x, v0.y, v0.z, v0.w, v1.x, v1.y, v1.z, v1.w};
    float h[8], l[8];
#pragma unroll
    for (int i = 0; i < 8; ++i) {
        h[i] = __bfloat162float(__float2bfloat16(f[i]));
        l[i] = f[i] - h[i];
    }
    hi.x = pkbf(h[0], h[1]); hi.y = pkbf(h[2], h[3]);
    hi.z = pkbf(h[4], h[5]); hi.w = pkbf(h[6], h[7]);
    lo.x = pkbf(l[0], l[1]); lo.y = pkbf(l[2], l[3]);
    lo.z = pkbf(l[4], l[5]); lo.w = pkbf(l[6], l[7]);
}

// ---------------- HMMA (mma.sync) 16x8x16 bf16 -------------------------------
__device__ __forceinline__ void mma16816(float* d, uint32_t a0, uint32_t a1,
                                         uint32_t a2, uint32_t a3,
                                         uint32_t b0, uint32_t b1) {
    asm volatile(
        "mma.sync.aligned.m16n8k16.row.col.f32.bf16.bf16.f32 "
        "{%0,%1,%2,%3},{%4,%5,%6,%7},{%8,%9},{%0,%1,%2,%3};"
        : "+f"(d[0]), "+f"(d[1]), "+f"(d[2]), "+f"(d[3])
        : "r"(a0), "r"(a1), "r"(a2), "r"(a3), "r"(b0), "r"(b1));
}

// ---------------- decoder GEMM via mma.sync (3-term bf16 compensation) -------
__global__ void __launch_bounds__(256, 1) k_mma(
    const float* __restrict__ X, const float* __restrict__ W,
    const float* __restrict__ bias, float* __restrict__ out, int ldc) {
    __shared__ __align__(16) char sm[40960];
    const int tid = threadIdx.x;
    const int wid = tid >> 5, lid = tid & 31;
    const int m0 = blockIdx.x * 128;
    const int n0 = blockIdx.y * 128;
    const int warpM = wid >> 2;
    const int warpN = wid & 3;
    const int laneR = lid >> 2;
    const int laneC2 = (lid & 3) * 2;

    const int lrow = tid >> 1;
    const int lseg = tid & 1;
    const float* arow = X + (size_t)(m0 + lrow) * 1024 + lseg * 16;
    const float* brow = W + (size_t)(n0 + lrow) * 1024 + lseg * 16;
    const int sst = lrow * 80 + lseg * 32;

    float acc[4][4][4];
#pragma unroll
    for (int a = 0; a < 4; ++a)
#pragma unroll
        for (int b = 0; b < 4; ++b)
#pragma unroll
            for (int c = 0; c < 4; ++c) acc[a][b][c] = 0.f;

    float4 ra[4], rb[4];
#pragma unroll
    for (int i = 0; i < 4; ++i) {
        ra[i] = *(const float4*)(arow + i * 4);
        rb[i] = *(const float4*)(brow + i * 4);
    }

    const int NCH = 1024 / 32;
    for (int kc = 0; kc < NCH; ++kc) {
        {
            uint4 h0, l0, h1, l1;
            cvt8(ra[0], ra[1], h0, l0);
            cvt8(ra[2], ra[3], h1, l1);
            *(uint4*)(sm + sst) = h0;
            *(uint4*)(sm + sst + 16) = h1;
            *(uint4*)(sm + 10240 + sst) = l0;
            *(uint4*)(sm + 10240 + sst + 16) = l1;
            cvt8(rb[0], rb[1], h0, l0);
            cvt8(rb[2], rb[3], h1, l1);
            *(uint4*)(sm + 20480 + sst) = h0;
            *(uint4*)(sm + 20480 + sst + 16) = h1;
            *(uint4*)(sm + 30720 + sst) = l0;
            *(uint4*)(sm + 30720 + sst + 16) = l1;
        }
        __syncthreads();
        if (kc + 1 < NCH) {
            const float* an = arow + (kc + 1) * 32;
            const float* bn = brow + (kc + 1) * 32;
#pragma unroll
            for (int i = 0; i < 4; ++i) {
                ra[i] = *(const float4*)(an + i * 4);
                rb[i] = *(const float4*)(bn + i * 4);
            }
        }
#pragma unroll
        for (int ks = 0; ks < 2; ++ks) {
            uint32_t ah[4][4], al[4][4], bh[4][2], bl[4][2];
#pragma unroll
            for (int mt = 0; mt < 4; ++mt) {
                int hb = (warpM * 64 + mt * 16 + laneR) * 40 + ks * 16 + laneC2;
                const char* pA = sm + hb * 2;
#pragma unroll
                for (int q = 0; q < 4; ++q) {
                    int off = ((q & 1) ? 8 * 80 : 0) + ((q & 2) ? 16 : 0);
                    ah[mt][q] = *(const uint32_t*)(pA + off);
                    al[mt][q] = *(const uint32_t*)(pA + 10240 + off);
                }
            }
#pragma unroll
            for (int nt = 0; nt < 4; ++nt) {
                int hb = (warpN * 32 + nt * 8 + laneR) * 40 + ks * 16 + laneC2;
                const char* pB = sm + 20480 + hb * 2;
                bh[nt][0] = *(const uint32_t*)(pB);
                bh[nt][1] = *(const uint32_t*)(pB + 16);
                bl[nt][0] = *(const uint32_t*)(pB + 10240);
                bl[nt][1] = *(const uint32_t*)(pB + 10240 + 16);
            }
#pragma unroll
            for (int mt = 0; mt < 4; ++mt)
#pragma unroll
                for (int nt = 0; nt < 4; ++nt)
                    mma16816(acc[mt][nt], ah[mt][0], ah[mt][1], ah[mt][2], ah[mt][3],
                             bh[nt][0], bh[nt][1]);
#pragma unroll
            for (int mt = 0; mt < 4; ++mt)
#pragma unroll
                for (int nt = 0; nt < 4; ++nt)
                    mma16816(acc[mt][nt], ah[mt][0], ah[mt][1], ah[mt][2], ah[mt][3],
                             bl[nt][0], bl[nt][1]);
#pragma unroll
            for (int mt = 0; mt < 4; ++mt)
#pragma unroll
                for (int nt = 0; nt < 4; ++nt)
                    mma16816(acc[mt][nt], al[mt][0], al[mt][1], al[mt][2], al[mt][3],
                             bh[nt][0], bh[nt][1]);
        }
        __syncthreads();
    }

#pragma unroll
    for (int mt = 0; mt < 4; ++mt) {
        int m = m0 + warpM * 64 + mt * 16 + laneR;
#pragma unroll
        for (int nt = 0; nt < 4; ++nt) {
            int n = n0 + warpN * 32 + nt * 8 + laneC2;
            float bx = bias[n], by = bias[n + 1];
            *(float2*)(out + (size_t)m * ldc + n) =
                make_float2(acc[mt][nt][0] + bx, acc[mt][nt][1] + by);
            *(float2*)(out + (size_t)(m + 8) * ldc + n) =
                make_float2(acc[mt][nt][2] + bx, acc[mt][nt][3] + by);
        }
    }
}

// ---------------- xg precompute GEMM (exact fp32, f32x2) ---------------------
__global__ void __launch_bounds__(256, 2) k_gemm_xg(
    const float* __restrict__ X, const float* __restrict__ Wd,
    float* __restrict__ out) {
    __shared__ __align__(16) float sa[16][132];
    __shared__ __align__(16) float sb[16][132];
    const int m0 = blockIdx.x * 128;
    const int n0 = blockIdx.y * 128;
    const int tid = threadIdx.x;
    const int tn = tid & 15, tm = tid >> 4;
    unsigned long long acc[8][4];
#pragma unroll
    for (int i = 0; i < 8; i++)
#pragma unroll
        for (int p = 0; p < 4; p++) acc[i][p] = 0ULL;

    float4 pa[2], pb[2];
#pragma unroll
    for (int i = 0; i < 2; ++i) {
        int lid = tid + i * 256;
        int row = lid >> 2, kq = lid & 3;
        pa[i] = *(const float4*)(X + (size_t)(m0 + row) * NHID + kq * 4);
        pb[i] = *(const float4*)(Wd + (size_t)(n0 + row) * NHID + kq * 4);
    }
    for (int k0 = 0; k0 < NHID; k0 += 16) {
#pragma unroll
        for (int i = 0; i < 2; ++i) {
            int lid = tid + i * 256;
            int row = lid >> 2, kq = lid & 3;
            sa[kq * 4 + 0][row] = pa[i].x; sa[kq * 4 + 1][row] = pa[i].y;
            sa[kq * 4 + 2][row] = pa[i].z; sa[kq * 4 + 3][row] = pa[i].w;
            sb[kq * 4 + 0][row] = pb[i].x; sb[kq * 4 + 1][row] = pb[i].y;
            sb[kq * 4 + 2][row] = pb[i].z; sb[kq * 4 + 3][row] = pb[i].w;
        }
        __syncthreads();
        if (k0 + 16 < NHID) {
#pragma unroll
            for (int i = 0; i < 2; ++i) {
                int lid = tid + i * 256;
                int row = lid >> 2, kq = lid & 3;
                pa[i] = *(const float4*)(X + (size_t)(m0 + row) * NHID + (k0 + 16) + kq * 4);
                pb[i] = *(const float4*)(Wd + (size_t)(n0 + row) * NHID + (k0 + 16) + kq * 4);
            }
        }
#pragma unroll
        for (int k = 0; k < 16; ++k) {
            unsigned long long b2[4];
#pragma unroll
            for (int p = 0; p < 4; ++p)
                b2[p] = *(const unsigned long long*)&sb[k][p * 32 + tn * 2];
#pragma unroll
            for (int i = 0; i < 8; ++i) {
                unsigned long long as = splat2(sa[k][tm * 8 + i]);
#pragma unroll
                for (int p = 0; p < 4; ++p) ffma2(acc[i][p], as, b2[p]);
            }
        }
        __syncthreads();
    }
#pragma unroll
    for (int i = 0; i < 8; ++i) {
        int m = m0 + tm * 8 + i;
#pragma unroll
        for (int p = 0; p < 4; ++p) {
            int nn = n0 + p * 32 + tn * 2;
            float2 v = unpk(acc[i][p]);
            *(float2*)(out + (size_t)m * (NB * 4 * BS) + nn) = v;
        }
    }
}

// ---------------- embedding gather ------------------------------------------
__global__ void k_embed(const int* __restrict__ tokens, const float* __restrict__ embW,
                        float* __restrict__ x) {
    int tb = blockIdx.x;
    int tok = tokens[tb];
    const float4* src = (const float4*)(embW + (size_t)tok * NINP);
    float4* dst = (float4*)(x + (size_t)tb * NINP);
    dst[threadIdx.x] = src[threadIdx.x];
}

// ---------------- padded-flag grid barrier (release/acquire) -----------------
__device__ __forceinline__ void gbar(unsigned &gen) {
    __syncthreads();
    ++gen;
    if (threadIdx.x == 0) {
        asm volatile("st.release.gpu.global.u32 [%0], %1;"
                     :: "l"(&g_flags[blockIdx.x * 32]), "r"(gen) : "memory");
    }
    if (threadIdx.x < NCTA) {
        unsigned v;
        do {
            asm volatile("ld.acquire.gpu.global.u32 %0, [%1];"
                         : "=r"(v) : "l"(&g_flags[threadIdx.x * 32]) : "memory");
        } while (v < gen);
    }
    __syncthreads();
}

// ---------------- persistent recurrence kernel v3 (one layer) ----------------
// grid 128 CTAs x 256 threads, ~172KB dynamic smem (1 CTA/SM, all co-resident).
#define SMEM_REC (43008 * 4)
__global__ void __launch_bounds__(256, 1) k_rec(
    const float* __restrict__ xg, const float* __restrict__ Whh_l,
    const float* __restrict__ bih_l, const float* __restrict__ bhh_l,
    const float* __restrict__ h0_l, const float* __restrict__ c0_l,
    const float* __restrict__ wq, const float* __restrict__ bq,
    const float* __restrict__ wk, const float* __restrict__ bk,
    const float* __restrict__ wv, const float* __restrict__ bv,
    const float* __restrict__ wfc, const float* __restrict__ bfc,
    const float* __restrict__ lng, const float* __restrict__ lnb,
    float* __restrict__ hbuf, float* __restrict__ hlbuf,
    float* __restrict__ ys,
    float* __restrict__ outH, float* __restrict__ outC) {
    extern __shared__ float smf[];
    float* swf  = smf;            // Whh slice [256 k][36 cols]  (9216 floats)
    float* sa2  = smf + 9216;     // h tile [64 bb][260]         (16640; MHA aliases)
    float* smw  = smf + 25856;    // q/k/v weights [48][256]     (12288)
    float* swfc = smf + 38144;    // wfc [256][16]               (4096)
    float* sbfc = smf + 42240;    // 256
    float* slng = smf + 42496;    // 256
    float* slnb = smf + 42752;    // 256

    __shared__ float sq2[2][DK], skk2[2][NB][DK], svv2[2][NB][DK];
    __shared__ float ssc2[2][NB], sp2[2][NB], so2[2][DK], sredh[2][4];

    const int tid = threadIdx.x;
    const int r = blockIdx.x;
    const int n = r & 3;
    const int j0 = (r >> 2) * 8;
    const int tj = tid & 7, tb2 = tid >> 3;
    const int j = j0 + tj;
    const int lane = tid & 31;

    // ---- one-time preloads ----
    {
        const float* W = Whh_l + (size_t)n * 4 * BS * BS;
#pragma unroll
        for (int e = 0; e < 8; ++e) {
            int idx = e * 256 + tid;
            int col = idx >> 6, kq = idx & 63;
            int g = col & 3, jj = col >> 2;
            float4 v = *(const float4*)(W + (size_t)(g * BS + j0 + jj) * BS + kq * 4);
            swf[(kq * 4 + 0) * 36 + col] = v.x;
            swf[(kq * 4 + 1) * 36 + col] = v.y;
            swf[(kq * 4 + 2) * 36 + col] = v.z;
            swf[(kq * 4 + 3) * 36 + col] = v.w;
        }
#pragma unroll
        for (int i = 0; i < 4; ++i) {
            ((float4*)smw)[tid + i * 256] = ((const float4*)wq)[tid + i * 256];
            ((float4*)(smw + 4096))[tid + i * 256] = ((const float4*)wk)[tid + i * 256];
            ((float4*)(smw + 8192))[tid + i * 256] = ((const float4*)wv)[tid + i * 256];
            ((float4*)swfc)[tid + i * 256] = ((const float4*)wfc)[tid + i * 256];
        }
        sbfc[tid] = bfc[tid];
        slng[tid] = lng[tid];
        slnb[tid] = lnb[tid];
    }

    // biases + c registers
    const float b_i = bih_l[n * 4 * BS + 0 * BS + j] + bhh_l[n * 4 * BS + 0 * BS + j];
    const float b_f = bih_l[n * 4 * BS + 1 * BS + j] + bhh_l[n * 4 * BS + 1 * BS + j];
    const float b_g = bih_l[n * 4 * BS + 2 * BS + j] + bhh_l[n * 4 * BS + 2 * BS + j];
    const float b_o = bih_l[n * 4 * BS + 3 * BS + j] + bhh_l[n * 4 * BS + 3 * BS + j];
    float creg[2];
    creg[0] = c0_l[(tb2 * 2 + 0) * NHID + n * BS + j];
    creg[1] = c0_l[(tb2 * 2 + 1) * NHID + n * BS + j];

    unsigned bgen = g_flags[r * 32];

    // h0 publish
    {
        int base = (r * 256 + tid) * 2;
        float2 v = *(const float2*)(h0_l + base);
        __stcg((float2*)(hbuf + base), v);
    }

    // xg prefetch for t=0
    float xgv[2][4];
    {
        const float* xg_t = xg;
#pragma unroll
        for (int bi = 0; bi < 2; ++bi) {
            const float* xr = xg_t + (size_t)(tb2 * 2 + bi) * 4096 + n * 1024 + j;
            xgv[bi][0] = __ldg(xr);       xgv[bi][1] = __ldg(xr + 256);
            xgv[bi][2] = __ldg(xr + 512); xgv[bi][3] = __ldg(xr + 768);
        }
    }
    gbar(bgen);

    // MHA half-CTA constants
    const int htid = tid & 127;
    const int half = tid >> 7;
    const int item = r + half * 128;
    const int nn2 = item >> 6;
    const int bb2 = item & 63;
    float* sh = sa2 + half * 1088;
#define HBAR() asm volatile("bar.sync %0, 128;" :: "r"(half + 1) : "memory")

    for (int t = 0; t < T; ++t) {
        // ===== gates phase =====
#pragma unroll 4
        for (int i = 0; i < 16; ++i) {
            int idx = tid + i * 256;
            int bb = idx >> 6, kq = idx & 63;
            float4 v = __ldcg((const float4*)(hbuf + (size_t)bb * NHID + n * BS) + kq);
            *(float4*)&sa2[bb * 260 + kq * 4] = v;
        }
        __syncthreads();

        unsigned long long a00 = pack2(xgv[0][0] + b_i, xgv[0][1] + b_f);
        unsigned long long a01 = pack2(xgv[0][2] + b_g, xgv[0][3] + b_o);
        unsigned long long a10 = pack2(xgv[1][0] + b_i, xgv[1][1] + b_f);
        unsigned long long a11 = pack2(xgv[1][2] + b_g, xgv[1][3] + b_o);
        const float* s0 = &sa2[(tb2 * 2 + 0) * 260];
        const float* s1 = &sa2[(tb2 * 2 + 1) * 260];
        const float* wrow = &swf[tj * 4];
#pragma unroll 8
        for (int k = 0; k < 256; ++k) {
            ulonglong2 wv = *(const ulonglong2*)(wrow + k * 36);
            unsigned long long as0 = splat2(s0[k]);
            unsigned long long as1 = splat2(s1[k]);
            ffma2(a00, as0, wv.x); ffma2(a01, as0, wv.y);
            ffma2(a10, as1, wv.x); ffma2(a11, as1, wv.y);
        }
        {
            float2 g01 = unpk(a00), g23 = unpk(a01);
            float cn = sigmoidf_(g01.y) * creg[0] + sigmoidf_(g01.x) * tanhf(g23.x);
            creg[0] = cn;
            __stcg(hlbuf + (tb2 * 2 + 0) * NHID + n * BS + j,
                   sigmoidf_(g23.y) * tanhf(cn));
            g01 = unpk(a10); g23 = unpk(a11);
            cn = sigmoidf_(g01.y) * creg[1] + sigmoidf_(g01.x) * tanhf(g23.x);
            creg[1] = cn;
            __stcg(hlbuf + (tb2 * 2 + 1) * NHID + n * BS + j,
                   sigmoidf_(g23.y) * tanhf(cn));
        }
        gbar(bgen);

        // ===== MHA phase (two items in parallel half-CTAs) =====
        float* ys_t = ys + (size_t)t * B * NHID;
        {
            const float4* src = (const float4*)(hlbuf + (size_t)bb2 * NHID);
            ((float4*)sh)[htid] = __ldcg(src + htid);
            ((float4*)sh)[htid + 128] = __ldcg(src + htid + 128);
        }
        HBAR();
        for (int w = htid; w < 144; w += 128) {
            const float *hv, *wr; float* dst; float bpv;
            if (w < 16) { wr = smw + w * 256; hv = sh + nn2 * 256;
                          dst = &sq2[half][w]; bpv = __ldg(bq + w); }
            else if (w < 80) { int m = (w - 16) >> 4, d = (w - 16) & 15;
                               wr = smw + 4096 + d * 256; hv = sh + m * 256;
                               dst = &skk2[half][m][d]; bpv = __ldg(bk + d); }
            else { int m = (w - 80) >> 4, d = (w - 80) & 15;
                   wr = smw + 8192 + d * 256; hv = sh + m * 256;
                   dst = &svv2[half][m][d]; bpv = __ldg(bv + d); }
            float a0 = 0, a1 = 0, a2 = 0, a3 = 0;
#pragma unroll 8
            for (int jj = 0; jj < 256; jj += 4) {
                a0 += hv[jj] * wr[jj];         a1 += hv[jj + 1] * wr[jj + 1];
                a2 += hv[jj + 2] * wr[jj + 2]; a3 += hv[jj + 3] * wr[jj + 3];
            }
            *dst = a0 + a1 + a2 + a3 + bpv;
        }
        HBAR();
        if (htid < 4) {
            float s = 0;
#pragma unroll
            for (int d = 0; d < DK; ++d) s += sq2[half][d] * skk2[half][htid][d];
            ssc2[half][htid] = s * 0.25f;
        }
        HBAR();
        if (htid < 4) {
            float mx = fmaxf(fmaxf(ssc2[half][0], ssc2[half][1]),
                             fmaxf(ssc2[half][2], ssc2[half][3]));
            float sum = expf(ssc2[half][0] - mx) + expf(ssc2[half][1] - mx) +
                        expf(ssc2[half][2] - mx) + expf(ssc2[half][3] - mx);
            sp2[half][htid] = expf(ssc2[half][htid] - mx) / sum;
        }
        HBAR();
        if (htid < DK) {
            float o = 0;
#pragma unroll
            for (int m = 0; m < NB; ++m) o += sp2[half][m] * svv2[half][m][htid];
            so2[half][htid] = o;
        }
        HBAR();
        float v0 = sbfc[htid] + sh[nn2 * 256 + htid];
        float v1 = sbfc[htid + 128] + sh[nn2 * 256 + htid + 128];
#pragma unroll
        for (int d = 0; d < DK; ++d) {
            v0 += so2[half][d] * swfc[htid * DK + d];
            v1 += so2[half][d] * swfc[(htid + 128) * DK + d];
        }
        float s = v0 + v1;
#pragma unroll
        for (int off = 16; off; off >>= 1) s += __shfl_down_sync(0xffffffffu, s, off);
        if (lane == 0) sredh[half][htid >> 5] = s;
        HBAR();
        float mu = (sredh[half][0] + sredh[half][1] + sredh[half][2] + sredh[half][3])
                   * (1.f / BS);
        HBAR();
        float dv0 = v0 - mu, dv1 = v1 - mu;
        float s2 = dv0 * dv0 + dv1 * dv1;
#pragma unroll
        for (int off = 16; off; off >>= 1) s2 += __shfl_down_sync(0xffffffffu, s2, off);
        if (lane == 0) sredh[half][htid >> 5] = s2;
        HBAR();
        float var = (sredh[half][0] + sredh[half][1] + sredh[half][2] + sredh[half][3])
                    * (1.f / BS);
        float rstd = rsqrtf(var + 1e-5f);
        float y0 = dv0 * rstd * slng[htid] + slnb[htid];
        float y1 = dv1 * rstd * slng[htid + 128] + slnb[htid + 128];
        int i0 = bb2 * NHID + nn2 * 256 + htid;
        __stcg(hbuf + i0, y0);       ys_t[i0] = y0;
        __stcg(hbuf + i0 + 128, y1); ys_t[i0 + 128] = y1;

        // prefetch xg for t+1 (independent of barrier)
        if (t + 1 < T) {
            const float* xg_t = xg + (size_t)(t + 1) * B * 4096;
#pragma unroll
            for (int bi = 0; bi < 2; ++bi) {
                const float* xr = xg_t + (size_t)(tb2 * 2 + bi) * 4096 + n * 1024 + j;
                xgv[bi][0] = __ldg(xr);       xgv[bi][1] = __ldg(xr + 256);
                xgv[bi][2] = __ldg(xr + 512); xgv[bi][3] = __ldg(xr + 768);
            }
        }
        gbar(bgen);
    }

    // final state writeout
    {
        int base = (r * 256 + tid) * 2;
        float2 v = __ldcg((const float2*)(hbuf + base));
        *(float2*)(outH + base) = v;
    }
    outC[(tb2 * 2 + 0) * NHID + n * BS + j] = creg[0];
    outC[(tb2 * 2 + 1) * NHID + n * BS + j] = creg[1];
#undef HBAR
}

// ---------------- host driver ------------------------------------------------
extern "C" void kernel_launch(void* const* d_in, const int* in_sizes, int n_in,
                              void* d_out, int out_size) {
    const int* tokens = (const int*)d_in[0];
    const float* h0 = (const float*)d_in[1];
    const float* c0 = (const float*)d_in[2];
    const float* embW = (const float*)d_in[3];
    const float* Wih = (const float*)d_in[4];
    const float* Whh = (const float*)d_in[5];
    const float* bih = (const float*)d_in[6];
    const float* bhh = (const float*)d_in[7];
    const float* wq = (const float*)d_in[8];
    const float* bq = (const float*)d_in[9];
    const float* wk = (const float*)d_in[10];
    const float* bk = (const float*)d_in[11];
    const float* wv = (const float*)d_in[12];
    const float* bv = (const float*)d_in[13];
    const float* wfc = (const float*)d_in[14];
    const float* bfc = (const float*)d_in[15];
    const float* lng = (const float*)d_in[16];
    const float* lnb = (const float*)d_in[17];
    const float* Wd = (const float*)d_in[18];
    const float* bd = (const float*)d_in[19];
    float* out = (float*)d_out;

    static int attr_set = 0;
    if (!attr_set) {
        cudaFuncSetAttribute(k_rec, cudaFuncAttributeMaxDynamicSharedMemorySize,
                             SMEM_REC);
        attr_set = 1;
    }

    float *xb, *xg, *hbuf, *hlbuf;
    cudaGetSymbolAddress((void**)&xb, g_xbuf);
    cudaGetSymbolAddress((void**)&xg, g_xg);
    cudaGetSymbolAddress((void**)&hbuf, g_h);
    cudaGetSymbolAddress((void**)&hlbuf, g_hl);
    float* x0 = xb;
    float* x1 = xb + (size_t)T * B * NHID;

    k_embed<<<T * B, 256>>>(tokens, embW, x0);

    const size_t DECN = (size_t)T * B * NTOK;
    for (int l = 0; l < NLAYERS; ++l) {
        const float* xin = (l == 0) ? x0 : x1;
        float* xout = (l == 0) ? x1 : x0;
        const float* Wih_l = Wih + (size_t)l * NB * 4 * BS * NINP;
        const float* Whh_l = Whh + (size_t)l * NB * 4 * BS * BS;
        const float* bih_l = bih + (size_t)l * NB * 4 * BS;
        const float* bhh_l = bhh + (size_t)l * NB * 4 * BS;
        k_gemm_xg<<<dim3(32, 32), 256>>>(xin, Wih_l, xg);
        k_rec<<<NCTA, 256, SMEM_REC>>>(xg, Whh_l, bih_l, bhh_l,
                                       h0 + (size_t)l * B * NHID,
                                       c0 + (size_t)l * B * NHID,
                                       wq, bq, wk, bk, wv, bv, wfc, bfc, lng, lnb,
                                       hbuf, hlbuf, xout,
                                       out + DECN + (size_t)l * B * NHID,
                                       out + DECN + (size_t)NLAYERS * B * NHID +
                                           (size_t)l * B * NHID);
    }
    k_mma<<<dim3(32, 250), 256>>>(x0, Wd, bd, out, NTOK);
}

// round 9
// speedup vs baseline: 1.4683x; 1.0285x over previous
#include <cuda_runtime.h>
#include <cuda_bf16.h>
#include <cstdint>

#define NLAYERS 2
#define NB 4
#define BS 256
#define NHID 1024
#define NINP 1024
#define NTOK 32000
#define T 64
#define B 64
#define DK 16
#define NCTA 128

// ---------------- scratch (device globals: no allocation allowed) ----------
__device__ float g_xbuf[2][(size_t)T * B * NHID];
__device__ float g_xg[(size_t)T * B * NB * 4 * BS];
__device__ float g_h[B * NHID];
__device__ float g_hl[B * NHID];
__device__ unsigned g_flags[NCTA * 32];   // one flag per 128B line
__device__ unsigned short g_wh[(size_t)NTOK * NHID];  // Wd bf16 hi
__device__ unsigned short g_wl[(size_t)NTOK * NHID];  // Wd bf16 lo
__device__ unsigned short g_xh[(size_t)T * B * NHID]; // X bf16 hi
__device__ unsigned short g_xl[(size_t)T * B * NHID]; // X bf16 lo

// ---------------- f32x2 helpers ---------------------------------------------
__device__ __forceinline__ unsigned long long splat2(float a) {
    unsigned long long r;
    unsigned int u = __float_as_uint(a);
    asm("mov.b64 %0, {%1, %1};" : "=l"(r) : "r"(u));
    return r;
}
__device__ __forceinline__ unsigned long long pack2(float x, float y) {
    unsigned long long r;
    asm("mov.b64 %0, {%1, %2};" : "=l"(r)
        : "r"(__float_as_uint(x)), "r"(__float_as_uint(y)));
    return r;
}
__device__ __forceinline__ void ffma2(unsigned long long &c, unsigned long long a,
                                      unsigned long long b) {
    asm("fma.rn.f32x2 %0, %1, %2, %0;" : "+l"(c) : "l"(a), "l"(b));
}
__device__ __forceinline__ float2 unpk(unsigned long long v) {
    unsigned int x, y;
    asm("mov.b64 {%0, %1}, %2;" : "=r"(x), "=r"(y) : "l"(v));
    return make_float2(__uint_as_float(x), __uint_as_float(y));
}
__device__ __forceinline__ float sigmoidf_(float x) { return 1.f / (1.f + expf(-x)); }

// ---------------- bf16 split helpers ----------------------------------------
__device__ __forceinline__ uint32_t pkbf(float a, float b) {
    __nv_bfloat162 t = __floats2bfloat162_rn(a, b);
    return *reinterpret_cast<uint32_t*>(&t);
}

// ---------------- fp32 -> (hi, lo) bf16 split precompute ---------------------
__global__ void k_cvt(const float4* __restrict__ src,
                      unsigned short* __restrict__ hi,
                      unsigned short* __restrict__ lo) {
    int idx = blockIdx.x * blockDim.x + threadIdx.x;
    float4 v = src[idx];
    float f[4] = {v.x, v.y, v.z, v.w};
    float h[4], l[4];
#pragma unroll
    for (int i = 0; i < 4; ++i) {
        h[i] = __bfloat162float(__float2bfloat16(f[i]));
        l[i] = f[i] - h[i];
    }
    uint2 hp, lp;
    hp.x = pkbf(h[0], h[1]); hp.y = pkbf(h[2], h[3]);
    lp.x = pkbf(l[0], l[1]); lp.y = pkbf(l[2], l[3]);
    *(uint2*)(hi + (size_t)idx * 4) = hp;
    *(uint2*)(lo + (size_t)idx * 4) = lp;
}

// ---------------- HMMA (mma.sync) 16x8x16 bf16 -------------------------------
__device__ __forceinline__ void mma16816(float* d, uint32_t a0, uint32_t a1,
                                         uint32_t a2, uint32_t a3,
                                         uint32_t b0, uint32_t b1) {
    asm volatile(
        "mma.sync.aligned.m16n8k16.row.col.f32.bf16.bf16.f32 "
        "{%0,%1,%2,%3},{%4,%5,%6,%7},{%8,%9},{%0,%1,%2,%3};"
        : "+f"(d[0]), "+f"(d[1]), "+f"(d[2]), "+f"(d[3])
        : "r"(a0), "r"(a1), "r"(a2), "r"(a3), "r"(b0), "r"(b1));
}

// ---------------- decoder GEMM v2: precomputed bf16 hi/lo planes -------------
// out = X @ W^T + bias. CTA 128x128, 8 warps (64x32 warp tile), K-chunk 32.
__global__ void __launch_bounds__(256, 1) k_mma(
    const unsigned short* __restrict__ Xh, const unsigned short* __restrict__ Xl,
    const unsigned short* __restrict__ Wh, const unsigned short* __restrict__ Wl,
    const float* __restrict__ bias, float* __restrict__ out, int ldc) {
    __shared__ __align__(16) char sm[40960];
    const int tid = threadIdx.x;
    const int wid = tid >> 5, lid = tid & 31;
    const int m0 = blockIdx.x * 128;
    const int n0 = blockIdx.y * 128;
    const int warpM = wid >> 2;
    const int warpN = wid & 3;
    const int laneR = lid >> 2;
    const int laneC2 = (lid & 3) * 2;

    const int lrow = tid >> 1;
    const int lseg = tid & 1;
    const unsigned short* arh = Xh + (size_t)(m0 + lrow) * 1024 + lseg * 16;
    const unsigned short* arl = Xl + (size_t)(m0 + lrow) * 1024 + lseg * 16;
    const unsigned short* brh = Wh + (size_t)(n0 + lrow) * 1024 + lseg * 16;
    const unsigned short* brl = Wl + (size_t)(n0 + lrow) * 1024 + lseg * 16;
    const int sst = lrow * 80 + lseg * 32;

    float acc[4][4][4];
#pragma unroll
    for (int a = 0; a < 4; ++a)
#pragma unroll
        for (int b = 0; b < 4; ++b)
#pragma unroll
            for (int c = 0; c < 4; ++c) acc[a][b][c] = 0.f;

    uint4 pah[2], pal[2], pbh[2], pbl[2];
#pragma unroll
    for (int i = 0; i < 2; ++i) {
        pah[i] = *(const uint4*)(arh + i * 8);
        pal[i] = *(const uint4*)(arl + i * 8);
        pbh[i] = *(const uint4*)(brh + i * 8);
        pbl[i] = *(const uint4*)(brl + i * 8);
    }

    const int NCH = 1024 / 32;
    for (int kc = 0; kc < NCH; ++kc) {
#pragma unroll
        for (int i = 0; i < 2; ++i) {
            *(uint4*)(sm + sst + i * 16) = pah[i];
            *(uint4*)(sm + 10240 + sst + i * 16) = pal[i];
            *(uint4*)(sm + 20480 + sst + i * 16) = pbh[i];
            *(uint4*)(sm + 30720 + sst + i * 16) = pbl[i];
        }
        __syncthreads();
        if (kc + 1 < NCH) {
            int koff = (kc + 1) * 32;
#pragma unroll
            for (int i = 0; i < 2; ++i) {
                pah[i] = *(const uint4*)(arh + koff + i * 8);
                pal[i] = *(const uint4*)(arl + koff + i * 8);
                pbh[i] = *(const uint4*)(brh + koff + i * 8);
                pbl[i] = *(const uint4*)(brl + koff + i * 8);
            }
        }
#pragma unroll
        for (int ks = 0; ks < 2; ++ks) {
            uint32_t ah[4][4], al[4][4], bh[4][2], bl[4][2];
#pragma unroll
            for (int mt = 0; mt < 4; ++mt) {
                int hb = (warpM * 64 + mt * 16 + laneR) * 40 + ks * 16 + laneC2;
                const char* pA = sm + hb * 2;
#pragma unroll
                for (int q = 0; q < 4; ++q) {
                    int off = ((q & 1) ? 8 * 80 : 0) + ((q & 2) ? 16 : 0);
                    ah[mt][q] = *(const uint32_t*)(pA + off);
                    al[mt][q] = *(const uint32_t*)(pA + 10240 + off);
                }
            }
#pragma unroll
            for (int nt = 0; nt < 4; ++nt) {
                int hb = (warpN * 32 + nt * 8 + laneR) * 40 + ks * 16 + laneC2;
                const char* pB = sm + 20480 + hb * 2;
                bh[nt][0] = *(const uint32_t*)(pB);
                bh[nt][1] = *(const uint32_t*)(pB + 16);
                bl[nt][0] = *(const uint32_t*)(pB + 10240);
                bl[nt][1] = *(const uint32_t*)(pB + 10240 + 16);
            }
#pragma unroll
            for (int mt = 0; mt < 4; ++mt)
#pragma unroll
                for (int nt = 0; nt < 4; ++nt)
                    mma16816(acc[mt][nt], ah[mt][0], ah[mt][1], ah[mt][2], ah[mt][3],
                             bh[nt][0], bh[nt][1]);
#pragma unroll
            for (int mt = 0; mt < 4; ++mt)
#pragma unroll
                for (int nt = 0; nt < 4; ++nt)
                    mma16816(acc[mt][nt], ah[mt][0], ah[mt][1], ah[mt][2], ah[mt][3],
                             bl[nt][0], bl[nt][1]);
#pragma unroll
            for (int mt = 0; mt < 4; ++mt)
#pragma unroll
                for (int nt = 0; nt < 4; ++nt)
                    mma16816(acc[mt][nt], al[mt][0], al[mt][1], al[mt][2], al[mt][3],
                             bh[nt][0], bh[nt][1]);
        }
        __syncthreads();
    }

#pragma unroll
    for (int mt = 0; mt < 4; ++mt) {
        int m = m0 + warpM * 64 + mt * 16 + laneR;
#pragma unroll
        for (int nt = 0; nt < 4; ++nt) {
            int n = n0 + warpN * 32 + nt * 8 + laneC2;
            float bx = bias[n], by = bias[n + 1];
            *(float2*)(out + (size_t)m * ldc + n) =
                make_float2(acc[mt][nt][0] + bx, acc[mt][nt][1] + by);
            *(float2*)(out + (size_t)(m + 8) * ldc + n) =
                make_float2(acc[mt][nt][2] + bx, acc[mt][nt][3] + by);
        }
    }
}

// ---------------- xg precompute GEMM (exact fp32, f32x2) ---------------------
__global__ void __launch_bounds__(256, 2) k_gemm_xg(
    const float* __restrict__ X, const float* __restrict__ Wd,
    float* __restrict__ out) {
    __shared__ __align__(16) float sa[16][132];
    __shared__ __align__(16) float sb[16][132];
    const int m0 = blockIdx.x * 128;
    const int n0 = blockIdx.y * 128;
    const int tid = threadIdx.x;
    const int tn = tid & 15, tm = tid >> 4;
    unsigned long long acc[8][4];
#pragma unroll
    for (int i = 0; i < 8; i++)
#pragma unroll
        for (int p = 0; p < 4; p++) acc[i][p] = 0ULL;

    float4 pa[2], pb[2];
#pragma unroll
    for (int i = 0; i < 2; ++i) {
        int lid = tid + i * 256;
        int row = lid >> 2, kq = lid & 3;
        pa[i] = *(const float4*)(X + (size_t)(m0 + row) * NHID + kq * 4);
        pb[i] = *(const float4*)(Wd + (size_t)(n0 + row) * NHID + kq * 4);
    }
    for (int k0 = 0; k0 < NHID; k0 += 16) {
#pragma unroll
        for (int i = 0; i < 2; ++i) {
            int lid = tid + i * 256;
            int row = lid >> 2, kq = lid & 3;
            sa[kq * 4 + 0][row] = pa[i].x; sa[kq * 4 + 1][row] = pa[i].y;
            sa[kq * 4 + 2][row] = pa[i].z; sa[kq * 4 + 3][row] = pa[i].w;
            sb[kq * 4 + 0][row] = pb[i].x; sb[kq * 4 + 1][row] = pb[i].y;
            sb[kq * 4 + 2][row] = pb[i].z; sb[kq * 4 + 3][row] = pb[i].w;
        }
        __syncthreads();
        if (k0 + 16 < NHID) {
#pragma unroll
            for (int i = 0; i < 2; ++i) {
                int lid = tid + i * 256;
                int row = lid >> 2, kq = lid & 3;
                pa[i] = *(const float4*)(X + (size_t)(m0 + row) * NHID + (k0 + 16) + kq * 4);
                pb[i] = *(const float4*)(Wd + (size_t)(n0 + row) * NHID + (k0 + 16) + kq * 4);
            }
        }
#pragma unroll
        for (int k = 0; k < 16; ++k) {
            unsigned long long b2[4];
#pragma unroll
            for (int p = 0; p < 4; ++p)
                b2[p] = *(const unsigned long long*)&sb[k][p * 32 + tn * 2];
#pragma unroll
            for (int i = 0; i < 8; ++i) {
                unsigned long long as = splat2(sa[k][tm * 8 + i]);
#pragma unroll
                for (int p = 0; p < 4; ++p) ffma2(acc[i][p], as, b2[p]);
            }
        }
        __syncthreads();
    }
#pragma unroll
    for (int i = 0; i < 8; ++i) {
        int m = m0 + tm * 8 + i;
#pragma unroll
        for (int p = 0; p < 4; ++p) {
            int nn = n0 + p * 32 + tn * 2;
            float2 v = unpk(acc[i][p]);
            *(float2*)(out + (size_t)m * (NB * 4 * BS) + nn) = v;
        }
    }
}

// ---------------- embedding gather ------------------------------------------
__global__ void k_embed(const int* __restrict__ tokens, const float* __restrict__ embW,
                        float* __restrict__ x) {
    int tb = blockIdx.x;
    int tok = tokens[tb];
    const float4* src = (const float4*)(embW + (size_t)tok * NINP);
    float4* dst = (float4*)(x + (size_t)tb * NINP);
    dst[threadIdx.x] = src[threadIdx.x];
}

// ---------------- padded-flag grid barrier (release/acquire) -----------------
__device__ __forceinline__ void gbar(unsigned &gen) {
    __syncthreads();
    ++gen;
    if (threadIdx.x == 0) {
        asm volatile("st.release.gpu.global.u32 [%0], %1;"
                     :: "l"(&g_flags[blockIdx.x * 32]), "r"(gen) : "memory");
    }
    if (threadIdx.x < NCTA) {
        unsigned v;
        do {
            asm volatile("ld.acquire.gpu.global.u32 %0, [%1];"
                         : "=r"(v) : "l"(&g_flags[threadIdx.x * 32]) : "memory");
        } while (v < gen);
    }
    __syncthreads();
}

// ---------------- persistent recurrence kernel v3 (one layer) ----------------
#define SMEM_REC (43008 * 4)
__global__ void __launch_bounds__(256, 1) k_rec(
    const float* __restrict__ xg, const float* __restrict__ Whh_l,
    const float* __restrict__ bih_l, const float* __restrict__ bhh_l,
    const float* __restrict__ h0_l, const float* __restrict__ c0_l,
    const float* __restrict__ wq, const float* __restrict__ bq,
    const float* __restrict__ wk, const float* __restrict__ bk,
    const float* __restrict__ wv, const float* __restrict__ bv,
    const float* __restrict__ wfc, const float* __restrict__ bfc,
    const float* __restrict__ lng, const float* __restrict__ lnb,
    float* __restrict__ hbuf, float* __restrict__ hlbuf,
    float* __restrict__ ys,
    float* __restrict__ outH, float* __restrict__ outC) {
    extern __shared__ float smf[];
    float* swf  = smf;            // Whh slice [256 k][36 cols]
    float* sa2  = smf + 9216;     // h tile [64 bb][260] (MHA aliases)
    float* smw  = smf + 25856;    // q/k/v weights [48][256]
    float* swfc = smf + 38144;    // wfc [256][16]
    float* sbfc = smf + 42240;
    float* slng = smf + 42496;
    float* slnb = smf + 42752;

    __shared__ float sq2[2][DK], skk2[2][NB][DK], svv2[2][NB][DK];
    __shared__ float ssc2[2][NB], sp2[2][NB], so2[2][DK], sredh[2][4];

    const int tid = threadIdx.x;
    const int r = blockIdx.x;
    const int n = r & 3;
    const int j0 = (r >> 2) * 8;
    const int tj = tid & 7, tb2 = tid >> 3;
    const int j = j0 + tj;
    const int lane = tid & 31;

    {
        const float* W = Whh_l + (size_t)n * 4 * BS * BS;
#pragma unroll
        for (int e = 0; e < 8; ++e) {
            int idx = e * 256 + tid;
            int col = idx >> 6, kq = idx & 63;
            int g = col & 3, jj = col >> 2;
            float4 v = *(const float4*)(W + (size_t)(g * BS + j0 + jj) * BS + kq * 4);
            swf[(kq * 4 + 0) * 36 + col] = v.x;
            swf[(kq * 4 + 1) * 36 + col] = v.y;
            swf[(kq * 4 + 2) * 36 + col] = v.z;
            swf[(kq * 4 + 3) * 36 + col] = v.w;
        }
#pragma unroll
        for (int i = 0; i < 4; ++i) {
            ((float4*)smw)[tid + i * 256] = ((const float4*)wq)[tid + i * 256];
            ((float4*)(smw + 4096))[tid + i * 256] = ((const float4*)wk)[tid + i * 256];
            ((float4*)(smw + 8192))[tid + i * 256] = ((const float4*)wv)[tid + i * 256];
            ((float4*)swfc)[tid + i * 256] = ((const float4*)wfc)[tid + i * 256];
        }
        sbfc[tid] = bfc[tid];
        slng[tid] = lng[tid];
        slnb[tid] = lnb[tid];
    }

    const float b_i = bih_l[n * 4 * BS + 0 * BS + j] + bhh_l[n * 4 * BS + 0 * BS + j];
    const float b_f = bih_l[n * 4 * BS + 1 * BS + j] + bhh_l[n * 4 * BS + 1 * BS + j];
    const float b_g = bih_l[n * 4 * BS + 2 * BS + j] + bhh_l[n * 4 * BS + 2 * BS + j];
    const float b_o = bih_l[n * 4 * BS + 3 * BS + j] + bhh_l[n * 4 * BS + 3 * BS + j];
    float creg[2];
    creg[0] = c0_l[(tb2 * 2 + 0) * NHID + n * BS + j];
    creg[1] = c0_l[(tb2 * 2 + 1) * NHID + n * BS + j];

    unsigned bgen = g_flags[r * 32];

    {
        int base = (r * 256 + tid) * 2;
        float2 v = *(const float2*)(h0_l + base);
        __stcg((float2*)(hbuf + base), v);
    }

    float xgv[2][4];
    {
        const float* xg_t = xg;
#pragma unroll
        for (int bi = 0; bi < 2; ++bi) {
            const float* xr = xg_t + (size_t)(tb2 * 2 + bi) * 4096 + n * 1024 + j;
            xgv[bi][0] = __ldg(xr);       xgv[bi][1] = __ldg(xr + 256);
            xgv[bi][2] = __ldg(xr + 512); xgv[bi][3] = __ldg(xr + 768);
        }
    }
    gbar(bgen);

    const int htid = tid & 127;
    const int half = tid >> 7;
    const int item = r + half * 128;
    const int nn2 = item >> 6;
    const int bb2 = item & 63;
    float* sh = sa2 + half * 1088;
#define HBAR() asm volatile("bar.sync %0, 128;" :: "r"(half + 1) : "memory")

    for (int t = 0; t < T; ++t) {
#pragma unroll 4
        for (int i = 0; i < 16; ++i) {
            int idx = tid + i * 256;
            int bb = idx >> 6, kq = idx & 63;
            float4 v = __ldcg((const float4*)(hbuf + (size_t)bb * NHID + n * BS) + kq);
            *(float4*)&sa2[bb * 260 + kq * 4] = v;
        }
        __syncthreads();

        unsigned long long a00 = pack2(xgv[0][0] + b_i, xgv[0][1] + b_f);
        unsigned long long a01 = pack2(xgv[0][2] + b_g, xgv[0][3] + b_o);
        unsigned long long a10 = pack2(xgv[1][0] + b_i, xgv[1][1] + b_f);
        unsigned long long a11 = pack2(xgv[1][2] + b_g, xgv[1][3] + b_o);
        const float* s0 = &sa2[(tb2 * 2 + 0) * 260];
        const float* s1 = &sa2[(tb2 * 2 + 1) * 260];
        const float* wrow = &swf[tj * 4];
#pragma unroll 8
        for (int k = 0; k < 256; ++k) {
            ulonglong2 wv = *(const ulonglong2*)(wrow + k * 36);
            unsigned long long as0 = splat2(s0[k]);
            unsigned long long as1 = splat2(s1[k]);
            ffma2(a00, as0, wv.x); ffma2(a01, as0, wv.y);
            ffma2(a10, as1, wv.x); ffma2(a11, as1, wv.y);
        }
        {
            float2 g01 = unpk(a00), g23 = unpk(a01);
            float cn = sigmoidf_(g01.y) * creg[0] + sigmoidf_(g01.x) * tanhf(g23.x);
            creg[0] = cn;
            __stcg(hlbuf + (tb2 * 2 + 0) * NHID + n * BS + j,
                   sigmoidf_(g23.y) * tanhf(cn));
            g01 = unpk(a10); g23 = unpk(a11);
            cn = sigmoidf_(g01.y) * creg[1] + sigmoidf_(g01.x) * tanhf(g23.x);
            creg[1] = cn;
            __stcg(hlbuf + (tb2 * 2 + 1) * NHID + n * BS + j,
                   sigmoidf_(g23.y) * tanhf(cn));
        }
        gbar(bgen);

        float* ys_t = ys + (size_t)t * B * NHID;
        {
            const float4* src = (const float4*)(hlbuf + (size_t)bb2 * NHID);
            ((float4*)sh)[htid] = __ldcg(src + htid);
            ((float4*)sh)[htid + 128] = __ldcg(src + htid + 128);
        }
        HBAR();
        for (int w = htid; w < 144; w += 128) {
            const float *hv, *wr; float* dst; float bpv;
            if (w < 16) { wr = smw + w * 256; hv = sh + nn2 * 256;
                          dst = &sq2[half][w]; bpv = __ldg(bq + w); }
            else if (w < 80) { int m = (w - 16) >> 4, d = (w - 16) & 15;
                               wr = smw + 4096 + d * 256; hv = sh + m * 256;
                               dst = &skk2[half][m][d]; bpv = __ldg(bk + d); }
            else { int m = (w - 80) >> 4, d = (w - 80) & 15;
                   wr = smw + 8192 + d * 256; hv = sh + m * 256;
                   dst = &svv2[half][m][d]; bpv = __ldg(bv + d); }
            float a0 = 0, a1 = 0, a2 = 0, a3 = 0;
#pragma unroll 8
            for (int jj = 0; jj < 256; jj += 4) {
                a0 += hv[jj] * wr[jj];         a1 += hv[jj + 1] * wr[jj + 1];
                a2 += hv[jj + 2] * wr[jj + 2]; a3 += hv[jj + 3] * wr[jj + 3];
            }
            *dst = a0 + a1 + a2 + a3 + bpv;
        }
        HBAR();
        if (htid < 4) {
            float s = 0;
#pragma unroll
            for (int d = 0; d < DK; ++d) s += sq2[half][d] * skk2[half][htid][d];
            ssc2[half][htid] = s * 0.25f;
        }
        HBAR();
        if (htid < 4) {
            float mx = fmaxf(fmaxf(ssc2[half][0], ssc2[half][1]),
                             fmaxf(ssc2[half][2], ssc2[half][3]));
            float sum = expf(ssc2[half][0] - mx) + expf(ssc2[half][1] - mx) +
                        expf(ssc2[half][2] - mx) + expf(ssc2[half][3] - mx);
            sp2[half][htid] = expf(ssc2[half][htid] - mx) / sum;
        }
        HBAR();
        if (htid < DK) {
            float o = 0;
#pragma unroll
            for (int m = 0; m < NB; ++m) o += sp2[half][m] * svv2[half][m][htid];
            so2[half][htid] = o;
        }
        HBAR();
        float v0 = sbfc[htid] + sh[nn2 * 256 + htid];
        float v1 = sbfc[htid + 128] + sh[nn2 * 256 + htid + 128];
#pragma unroll
        for (int d = 0; d < DK; ++d) {
            v0 += so2[half][d] * swfc[htid * DK + d];
            v1 += so2[half][d] * swfc[(htid + 128) * DK + d];
        }
        float s = v0 + v1;
#pragma unroll
        for (int off = 16; off; off >>= 1) s += __shfl_down_sync(0xffffffffu, s, off);
        if (lane == 0) sredh[half][htid >> 5] = s;
        HBAR();
        float mu = (sredh[half][0] + sredh[half][1] + sredh[half][2] + sredh[half][3])
                   * (1.f / BS);
        HBAR();
        float dv0 = v0 - mu, dv1 = v1 - mu;
        float s2 = dv0 * dv0 + dv1 * dv1;
#pragma unroll
        for (int off = 16; off; off >>= 1) s2 += __shfl_down_sync(0xffffffffu, s2, off);
        if (lane == 0) sredh[half][htid >> 5] = s2;
        HBAR();
        float var = (sredh[half][0] + sredh[half][1] + sredh[half][2] + sredh[half][3])
                    * (1.f / BS);
        float rstd = rsqrtf(var + 1e-5f);
        float y0 = dv0 * rstd * slng[htid] + slnb[htid];
        float y1 = dv1 * rstd * slng[htid + 128] + slnb[htid + 128];
        int i0 = bb2 * NHID + nn2 * 256 + htid;
        __stcg(hbuf + i0, y0);       ys_t[i0] = y0;
        __stcg(hbuf + i0 + 128, y1); ys_t[i0 + 128] = y1;

        if (t + 1 < T) {
            const float* xg_t = xg + (size_t)(t + 1) * B * 4096;
#pragma unroll
            for (int bi = 0; bi < 2; ++bi) {
                const float* xr = xg_t + (size_t)(tb2 * 2 + bi) * 4096 + n * 1024 + j;
                xgv[bi][0] = __ldg(xr);       xgv[bi][1] = __ldg(xr + 256);
                xgv[bi][2] = __ldg(xr + 512); xgv[bi][3] = __ldg(xr + 768);
            }
        }
        gbar(bgen);
    }

    {
        int base = (r * 256 + tid) * 2;
        float2 v = __ldcg((const float2*)(hbuf + base));
        *(float2*)(outH + base) = v;
    }
    outC[(tb2 * 2 + 0) * NHID + n * BS + j] = creg[0];
    outC[(tb2 * 2 + 1) * NHID + n * BS + j] = creg[1];
#undef HBAR
}

// ---------------- host driver ------------------------------------------------
extern "C" void kernel_launch(void* const* d_in, const int* in_sizes, int n_in,
                              void* d_out, int out_size) {
    const int* tokens = (const int*)d_in[0];
    const float* h0 = (const float*)d_in[1];
    const float* c0 = (const float*)d_in[2];
    const float* embW = (const float*)d_in[3];
    const float* Wih = (const float*)d_in[4];
    const float* Whh = (const float*)d_in[5];
    const float* bih = (const float*)d_in[6];
    const float* bhh = (const float*)d_in[7];
    const float* wq = (const float*)d_in[8];
    const float* bq = (const float*)d_in[9];
    const float* wk = (const float*)d_in[10];
    const float* bk = (const float*)d_in[11];
    const float* wv = (const float*)d_in[12];
    const float* bv = (const float*)d_in[13];
    const float* wfc = (const float*)d_in[14];
    const float* bfc = (const float*)d_in[15];
    const float* lng = (const float*)d_in[16];
    const float* lnb = (const float*)d_in[17];
    const float* Wd = (const float*)d_in[18];
    const float* bd = (const float*)d_in[19];
    float* out = (float*)d_out;

    static int attr_set = 0;
    if (!attr_set) {
        cudaFuncSetAttribute(k_rec, cudaFuncAttributeMaxDynamicSharedMemorySize,
                             SMEM_REC);
        attr_set = 1;
    }

    float *xb, *xg, *hbuf, *hlbuf;
    unsigned short *wh, *wl, *xh, *xl;
    cudaGetSymbolAddress((void**)&xb, g_xbuf);
    cudaGetSymbolAddress((void**)&xg, g_xg);
    cudaGetSymbolAddress((void**)&hbuf, g_h);
    cudaGetSymbolAddress((void**)&hlbuf, g_hl);
    cudaGetSymbolAddress((void**)&wh, g_wh);
    cudaGetSymbolAddress((void**)&wl, g_wl);
    cudaGetSymbolAddress((void**)&xh, g_xh);
    cudaGetSymbolAddress((void**)&xl, g_xl);
    float* x0 = xb;
    float* x1 = xb + (size_t)T * B * NHID;

    // Wd -> bf16 hi/lo (independent of recurrence; off critical path logically)
    k_cvt<<<(NTOK * NHID / 4) / 256, 256>>>((const float4*)Wd, wh, wl);

    k_embed<<<T * B, 256>>>(tokens, embW, x0);

    const size_t DECN = (size_t)T * B * NTOK;
    for (int l = 0; l < NLAYERS; ++l) {
        const float* xin = (l == 0) ? x0 : x1;
        float* xout = (l == 0) ? x1 : x0;
        const float* Wih_l = Wih + (size_t)l * NB * 4 * BS * NINP;
        const float* Whh_l = Whh + (size_t)l * NB * 4 * BS * BS;
        const float* bih_l = bih + (size_t)l * NB * 4 * BS;
        const float* bhh_l = bhh + (size_t)l * NB * 4 * BS;
        k_gemm_xg<<<dim3(32, 32), 256>>>(xin, Wih_l, xg);
        k_rec<<<NCTA, 256, SMEM_REC>>>(xg, Whh_l, bih_l, bhh_l,
                                       h0 + (size_t)l * B * NHID,
                                       c0 + (size_t)l * B * NHID,
                                       wq, bq, wk, bk, wv, bv, wfc, bfc, lng, lnb,
                                       hbuf, hlbuf, xout,
                                       out + DECN + (size_t)l * B * NHID,
                                       out + DECN + (size_t)NLAYERS * B * NHID +
                                           (size_t)l * B * NHID);
    }
    // final activations -> bf16 hi/lo, then decoder on tensor cores
    k_cvt<<<((size_t)T * B * NHID / 4) / 256, 256>>>((const float4*)x0, xh, xl);
    k_mma<<<dim3(32, 250), 256>>>(xh, xl, wh, wl, bd, out, NTOK);
}

// round 10
// speedup vs baseline: 1.7697x; 1.2053x over previous
#include <cuda_runtime.h>
#include <cuda_fp16.h>
#include <cstdint>

#define NLAYERS 2
#define NB 4
#define BS 256
#define NHID 1024
#define NINP 1024
#define NTOK 32000
#define T 64
#define B 64
#define DK 16
#define NCTA 128

// ---------------- scratch (device globals: no allocation allowed) ----------
__device__ float g_xbuf[2][(size_t)T * B * NHID];
__device__ float g_xg[(size_t)T * B * NB * 4 * BS];
__device__ float g_h[B * NHID];
__device__ float g_hl[B * NHID];
__device__ unsigned g_flags[NCTA * 32];               // one flag per 128B line
__device__ unsigned short g_wh[(size_t)NTOK * NHID];  // Wd fp16 hi
__device__ unsigned short g_wl[(size_t)NTOK * NHID];  // Wd fp16 lo
__device__ unsigned short g_xh[(size_t)T * B * NHID]; // activations fp16 hi
__device__ unsigned short g_xl[(size_t)T * B * NHID]; // activations fp16 lo
__device__ unsigned short g_wihh[(size_t)NLAYERS * NB * 4 * BS * NINP]; // Wih hi
__device__ unsigned short g_wihl[(size_t)NLAYERS * NB * 4 * BS * NINP]; // Wih lo

// ---------------- f32x2 helpers ---------------------------------------------
__device__ __forceinline__ unsigned long long splat2(float a) {
    unsigned long long r;
    unsigned int u = __float_as_uint(a);
    asm("mov.b64 %0, {%1, %1};" : "=l"(r) : "r"(u));
    return r;
}
__device__ __forceinline__ unsigned long long pack2(float x, float y) {
    unsigned long long r;
    asm("mov.b64 %0, {%1, %2};" : "=l"(r)
        : "r"(__float_as_uint(x)), "r"(__float_as_uint(y)));
    return r;
}
__device__ __forceinline__ void ffma2(unsigned long long &c, unsigned long long a,
                                      unsigned long long b) {
    asm("fma.rn.f32x2 %0, %1, %2, %0;" : "+l"(c) : "l"(a), "l"(b));
}
__device__ __forceinline__ float2 unpk(unsigned long long v) {
    unsigned int x, y;
    asm("mov.b64 {%0, %1}, %2;" : "=r"(x), "=r"(y) : "l"(v));
    return make_float2(__uint_as_float(x), __uint_as_float(y));
}
__device__ __forceinline__ float sigmoidf_(float x) { return 1.f / (1.f + expf(-x)); }

// ---------------- fp32 -> (hi, lo) fp16 split precompute ---------------------
__global__ void k_cvt(const float4* __restrict__ src,
                      unsigned short* __restrict__ hi,
                      unsigned short* __restrict__ lo) {
    size_t idx = (size_t)blockIdx.x * blockDim.x + threadIdx.x;
    float4 v = src[idx];
    float f[4] = {v.x, v.y, v.z, v.w};
    __half h[4], l[4];
#pragma unroll
    for (int i = 0; i < 4; ++i) {
        h[i] = __float2half_rn(f[i]);
        l[i] = __float2half_rn(f[i] - __half2float(h[i]));
    }
    uint2 hp, lp;
    hp.x = ((uint32_t)*(unsigned short*)&h[1] << 16) | *(unsigned short*)&h[0];
    hp.y = ((uint32_t)*(unsigned short*)&h[3] << 16) | *(unsigned short*)&h[2];
    lp.x = ((uint32_t)*(unsigned short*)&l[1] << 16) | *(unsigned short*)&l[0];
    lp.y = ((uint32_t)*(unsigned short*)&l[3] << 16) | *(unsigned short*)&l[2];
    *(uint2*)(hi + idx * 4) = hp;
    *(uint2*)(lo + idx * 4) = lp;
}

// ---------------- HMMA fp16 + ldmatrix helpers -------------------------------
__device__ __forceinline__ void mma16816(float* d, uint32_t a0, uint32_t a1,
                                         uint32_t a2, uint32_t a3,
                                         uint32_t b0, uint32_t b1) {
    asm volatile(
        "mma.sync.aligned.m16n8k16.row.col.f32.f16.f16.f32 "
        "{%0,%1,%2,%3},{%4,%5,%6,%7},{%8,%9},{%0,%1,%2,%3};"
        : "+f"(d[0]), "+f"(d[1]), "+f"(d[2]), "+f"(d[3])
        : "r"(a0), "r"(a1), "r"(a2), "r"(a3), "r"(b0), "r"(b1));
}
__device__ __forceinline__ uint32_t smem_u32(const void* p) {
    uint32_t a;
    asm("{ .reg .u64 t; cvta.to.shared.u64 t, %1; cvt.u32.u64 %0, t; }"
        : "=r"(a) : "l"(p));
    return a;
}
__device__ __forceinline__ void ldsm4(uint32_t &r0, uint32_t &r1, uint32_t &r2,
                                      uint32_t &r3, uint32_t addr) {
    asm volatile("ldmatrix.sync.aligned.m8n8.x4.shared.b16 {%0,%1,%2,%3},[%4];"
                 : "=r"(r0), "=r"(r1), "=r"(r2), "=r"(r3) : "r"(addr));
}
__device__ __forceinline__ void ldsm2(uint32_t &r0, uint32_t &r1, uint32_t addr) {
    asm volatile("ldmatrix.sync.aligned.m8n8.x2.shared.b16 {%0,%1},[%2];"
                 : "=r"(r0), "=r"(r1) : "r"(addr));
}

// ---------------- tensor-core GEMM (fp16 3-term): out = X @ W^T (+bias) ------
// CTA 128x128, 8 warps (64x32 warp tile), K-chunk 32, ldmatrix fragment loads.
__global__ void __launch_bounds__(256, 1) k_mma(
    const unsigned short* __restrict__ Xh, const unsigned short* __restrict__ Xl,
    const unsigned short* __restrict__ Wh, const unsigned short* __restrict__ Wl,
    const float* __restrict__ bias, float* __restrict__ out, int ldc) {
    __shared__ __align__(16) char sm[40960];
    const uint32_t sbase = smem_u32(sm);
    const int tid = threadIdx.x;
    const int wid = tid >> 5, lid = tid & 31;
    const int m0 = blockIdx.x * 128;
    const int n0 = blockIdx.y * 128;
    const int warpM = wid >> 2;
    const int warpN = wid & 3;
    const int laneR = lid >> 2;
    const int laneC2 = (lid & 3) * 2;
    // ldmatrix per-lane address components
    const uint32_t aoff = (uint32_t)((lid & 15) * 80 + (lid >> 4) * 16);
    const uint32_t boff = (uint32_t)((lid & 7) * 80 + ((lid >> 3) & 1) * 16);

    const int lrow = tid >> 1;
    const int lseg = tid & 1;
    const unsigned short* arh = Xh + (size_t)(m0 + lrow) * 1024 + lseg * 16;
    const unsigned short* arl = Xl + (size_t)(m0 + lrow) * 1024 + lseg * 16;
    const unsigned short* brh = Wh + (size_t)(n0 + lrow) * 1024 + lseg * 16;
    const unsigned short* brl = Wl + (size_t)(n0 + lrow) * 1024 + lseg * 16;
    const int sst = lrow * 80 + lseg * 32;

    float acc[4][4][4];
#pragma unroll
    for (int a = 0; a < 4; ++a)
#pragma unroll
        for (int b = 0; b < 4; ++b)
#pragma unroll
            for (int c = 0; c < 4; ++c) acc[a][b][c] = 0.f;

    uint4 pah[2], pal[2], pbh[2], pbl[2];
#pragma unroll
    for (int i = 0; i < 2; ++i) {
        pah[i] = *(const uint4*)(arh + i * 8);
        pal[i] = *(const uint4*)(arl + i * 8);
        pbh[i] = *(const uint4*)(brh + i * 8);
        pbl[i] = *(const uint4*)(brl + i * 8);
    }

    const int NCH = 1024 / 32;
    for (int kc = 0; kc < NCH; ++kc) {
#pragma unroll
        for (int i = 0; i < 2; ++i) {
            *(uint4*)(sm + sst + i * 16) = pah[i];
            *(uint4*)(sm + 10240 + sst + i * 16) = pal[i];
            *(uint4*)(sm + 20480 + sst + i * 16) = pbh[i];
            *(uint4*)(sm + 30720 + sst + i * 16) = pbl[i];
        }
        __syncthreads();
        if (kc + 1 < NCH) {
            int koff = (kc + 1) * 32;
#pragma unroll
            for (int i = 0; i < 2; ++i) {
                pah[i] = *(const uint4*)(arh + koff + i * 8);
                pal[i] = *(const uint4*)(arl + koff + i * 8);
                pbh[i] = *(const uint4*)(brh + koff + i * 8);
                pbl[i] = *(const uint4*)(brl + koff + i * 8);
            }
        }
#pragma unroll
        for (int ks = 0; ks < 2; ++ks) {
            uint32_t ah[4][4], al[4][4], bh[4][2], bl[4][2];
#pragma unroll
            for (int mt = 0; mt < 4; ++mt) {
                uint32_t ad = sbase + (uint32_t)((warpM * 64 + mt * 16) * 80 +
                                                 ks * 32) + aoff;
                ldsm4(ah[mt][0], ah[mt][1], ah[mt][2], ah[mt][3], ad);
                ldsm4(al[mt][0], al[mt][1], al[mt][2], al[mt][3], ad + 10240);
            }
#pragma unroll
            for (int nt = 0; nt < 4; ++nt) {
                uint32_t bd_ = sbase + 20480u +
                               (uint32_t)((warpN * 32 + nt * 8) * 80 + ks * 32) + boff;
                ldsm2(bh[nt][0], bh[nt][1], bd_);
                ldsm2(bl[nt][0], bl[nt][1], bd_ + 10240);
            }
#pragma unroll
            for (int mt = 0; mt < 4; ++mt)
#pragma unroll
                for (int nt = 0; nt < 4; ++nt)
                    mma16816(acc[mt][nt], ah[mt][0], ah[mt][1], ah[mt][2], ah[mt][3],
                             bh[nt][0], bh[nt][1]);
#pragma unroll
            for (int mt = 0; mt < 4; ++mt)
#pragma unroll
                for (int nt = 0; nt < 4; ++nt)
                    mma16816(acc[mt][nt], ah[mt][0], ah[mt][1], ah[mt][2], ah[mt][3],
                             bl[nt][0], bl[nt][1]);
#pragma unroll
            for (int mt = 0; mt < 4; ++mt)
#pragma unroll
                for (int nt = 0; nt < 4; ++nt)
                    mma16816(acc[mt][nt], al[mt][0], al[mt][1], al[mt][2], al[mt][3],
                             bh[nt][0], bh[nt][1]);
        }
        __syncthreads();
    }

#pragma unroll
    for (int mt = 0; mt < 4; ++mt) {
        int m = m0 + warpM * 64 + mt * 16 + laneR;
#pragma unroll
        for (int nt = 0; nt < 4; ++nt) {
            int n = n0 + warpN * 32 + nt * 8 + laneC2;
            float bx = 0.f, by = 0.f;
            if (bias) { bx = bias[n]; by = bias[n + 1]; }
            *(float2*)(out + (size_t)m * ldc + n) =
                make_float2(acc[mt][nt][0] + bx, acc[mt][nt][1] + by);
            *(float2*)(out + (size_t)(m + 8) * ldc + n) =
                make_float2(acc[mt][nt][2] + bx, acc[mt][nt][3] + by);
        }
    }
}

// ---------------- embedding gather ------------------------------------------
__global__ void k_embed(const int* __restrict__ tokens, const float* __restrict__ embW,
                        float* __restrict__ x) {
    int tb = blockIdx.x;
    int tok = tokens[tb];
    const float4* src = (const float4*)(embW + (size_t)tok * NINP);
    float4* dst = (float4*)(x + (size_t)tb * NINP);
    dst[threadIdx.x] = src[threadIdx.x];
}

// ---------------- padded-flag grid barrier (release/acquire) -----------------
__device__ __forceinline__ void gbar(unsigned &gen) {
    __syncthreads();
    ++gen;
    if (threadIdx.x == 0) {
        asm volatile("st.release.gpu.global.u32 [%0], %1;"
                     :: "l"(&g_flags[blockIdx.x * 32]), "r"(gen) : "memory");
    }
    if (threadIdx.x < NCTA) {
        unsigned v;
        do {
            asm volatile("ld.acquire.gpu.global.u32 %0, [%1];"
                         : "=r"(v) : "l"(&g_flags[threadIdx.x * 32]) : "memory");
        } while (v < gen);
    }
    __syncthreads();
}

// ---------------- persistent recurrence kernel v3 (one layer) ----------------
#define SMEM_REC (43008 * 4)
__global__ void __launch_bounds__(256, 1) k_rec(
    const float* __restrict__ xg, const float* __restrict__ Whh_l,
    const float* __restrict__ bih_l, const float* __restrict__ bhh_l,
    const float* __restrict__ h0_l, const float* __restrict__ c0_l,
    const float* __restrict__ wq, const float* __restrict__ bq,
    const float* __restrict__ wk, const float* __restrict__ bk,
    const float* __restrict__ wv, const float* __restrict__ bv,
    const float* __restrict__ wfc, const float* __restrict__ bfc,
    const float* __restrict__ lng, const float* __restrict__ lnb,
    float* __restrict__ hbuf, float* __restrict__ hlbuf,
    float* __restrict__ ys,
    float* __restrict__ outH, float* __restrict__ outC) {
    extern __shared__ float smf[];
    float* swf  = smf;            // Whh slice [256 k][36 cols]
    float* sa2  = smf + 9216;     // h tile [64 bb][260] (MHA aliases)
    float* smw  = smf + 25856;    // q/k/v weights [48][256]
    float* swfc = smf + 38144;    // wfc [256][16]
    float* sbfc = smf + 42240;
    float* slng = smf + 42496;
    float* slnb = smf + 42752;

    __shared__ float sq2[2][DK], skk2[2][NB][DK], svv2[2][NB][DK];
    __shared__ float ssc2[2][NB], sp2[2][NB], so2[2][DK], sredh[2][4];

    const int tid = threadIdx.x;
    const int r = blockIdx.x;
    const int n = r & 3;
    const int j0 = (r >> 2) * 8;
    const int tj = tid & 7, tb2 = tid >> 3;
    const int j = j0 + tj;
    const int lane = tid & 31;

    {
        const float* W = Whh_l + (size_t)n * 4 * BS * BS;
#pragma unroll
        for (int e = 0; e < 8; ++e) {
            int idx = e * 256 + tid;
            int col = idx >> 6, kq = idx & 63;
            int g = col & 3, jj = col >> 2;
            float4 v = *(const float4*)(W + (size_t)(g * BS + j0 + jj) * BS + kq * 4);
            swf[(kq * 4 + 0) * 36 + col] = v.x;
            swf[(kq * 4 + 1) * 36 + col] = v.y;
            swf[(kq * 4 + 2) * 36 + col] = v.z;
            swf[(kq * 4 + 3) * 36 + col] = v.w;
        }
#pragma unroll
        for (int i = 0; i < 4; ++i) {
            ((float4*)smw)[tid + i * 256] = ((const float4*)wq)[tid + i * 256];
            ((float4*)(smw + 4096))[tid + i * 256] = ((const float4*)wk)[tid + i * 256];
            ((float4*)(smw + 8192))[tid + i * 256] = ((const float4*)wv)[tid + i * 256];
            ((float4*)swfc)[tid + i * 256] = ((const float4*)wfc)[tid + i * 256];
        }
        sbfc[tid] = bfc[tid];
        slng[tid] = lng[tid];
        slnb[tid] = lnb[tid];
    }

    const float b_i = bih_l[n * 4 * BS + 0 * BS + j] + bhh_l[n * 4 * BS + 0 * BS + j];
    const float b_f = bih_l[n * 4 * BS + 1 * BS + j] + bhh_l[n * 4 * BS + 1 * BS + j];
    const float b_g = bih_l[n * 4 * BS + 2 * BS + j] + bhh_l[n * 4 * BS + 2 * BS + j];
    const float b_o = bih_l[n * 4 * BS + 3 * BS + j] + bhh_l[n * 4 * BS + 3 * BS + j];
    float creg[2];
    creg[0] = c0_l[(tb2 * 2 + 0) * NHID + n * BS + j];
    creg[1] = c0_l[(tb2 * 2 + 1) * NHID + n * BS + j];

    unsigned bgen = g_flags[r * 32];

    {
        int base = (r * 256 + tid) * 2;
        float2 v = *(const float2*)(h0_l + base);
        __stcg((float2*)(hbuf + base), v);
    }

    float xgv[2][4];
    {
        const float* xg_t = xg;
#pragma unroll
        for (int bi = 0; bi < 2; ++bi) {
            const float* xr = xg_t + (size_t)(tb2 * 2 + bi) * 4096 + n * 1024 + j;
            xgv[bi][0] = __ldg(xr);       xgv[bi][1] = __ldg(xr + 256);
            xgv[bi][2] = __ldg(xr + 512); xgv[bi][3] = __ldg(xr + 768);
        }
    }
    gbar(bgen);

    const int htid = tid & 127;
    const int half = tid >> 7;
    const int item = r + half * 128;
    const int nn2 = item >> 6;
    const int bb2 = item & 63;
    float* sh = sa2 + half * 1088;
#define HBAR() asm volatile("bar.sync %0, 128;" :: "r"(half + 1) : "memory")

    for (int t = 0; t < T; ++t) {
#pragma unroll 4
        for (int i = 0; i < 16; ++i) {
            int idx = tid + i * 256;
            int bb = idx >> 6, kq = idx & 63;
            float4 v = __ldcg((const float4*)(hbuf + (size_t)bb * NHID + n * BS) + kq);
            *(float4*)&sa2[bb * 260 + kq * 4] = v;
        }
        __syncthreads();

        unsigned long long a00 = pack2(xgv[0][0] + b_i, xgv[0][1] + b_f);
        unsigned long long a01 = pack2(xgv[0][2] + b_g, xgv[0][3] + b_o);
        unsigned long long a10 = pack2(xgv[1][0] + b_i, xgv[1][1] + b_f);
        unsigned long long a11 = pack2(xgv[1][2] + b_g, xgv[1][3] + b_o);
        const float* s0 = &sa2[(tb2 * 2 + 0) * 260];
        const float* s1 = &sa2[(tb2 * 2 + 1) * 260];
        const float* wrow = &swf[tj * 4];
#pragma unroll 8
        for (int k = 0; k < 256; ++k) {
            ulonglong2 wv = *(const ulonglong2*)(wrow + k * 36);
            unsigned long long as0 = splat2(s0[k]);
            unsigned long long as1 = splat2(s1[k]);
            ffma2(a00, as0, wv.x); ffma2(a01, as0, wv.y);
            ffma2(a10, as1, wv.x); ffma2(a11, as1, wv.y);
        }
        {
            float2 g01 = unpk(a00), g23 = unpk(a01);
            float cn = sigmoidf_(g01.y) * creg[0] + sigmoidf_(g01.x) * tanhf(g23.x);
            creg[0] = cn;
            __stcg(hlbuf + (tb2 * 2 + 0) * NHID + n * BS + j,
                   sigmoidf_(g23.y) * tanhf(cn));
            g01 = unpk(a10); g23 = unpk(a11);
            cn = sigmoidf_(g01.y) * creg[1] + sigmoidf_(g01.x) * tanhf(g23.x);
            creg[1] = cn;
            __stcg(hlbuf + (tb2 * 2 + 1) * NHID + n * BS + j,
                   sigmoidf_(g23.y) * tanhf(cn));
        }
        gbar(bgen);

        float* ys_t = ys + (size_t)t * B * NHID;
        {
            const float4* src = (const float4*)(hlbuf + (size_t)bb2 * NHID);
            ((float4*)sh)[htid] = __ldcg(src + htid);
            ((float4*)sh)[htid + 128] = __ldcg(src + htid + 128);
        }
        HBAR();
        for (int w = htid; w < 144; w += 128) {
            const float *hv, *wr; float* dst; float bpv;
            if (w < 16) { wr = smw + w * 256; hv = sh + nn2 * 256;
                          dst = &sq2[half][w]; bpv = __ldg(bq + w); }
            else if (w < 80) { int m = (w - 16) >> 4, d = (w - 16) & 15;
                               wr = smw + 4096 + d * 256; hv = sh + m * 256;
                               dst = &skk2[half][m][d]; bpv = __ldg(bk + d); }
            else { int m = (w - 80) >> 4, d = (w - 80) & 15;
                   wr = smw + 8192 + d * 256; hv = sh + m * 256;
                   dst = &svv2[half][m][d]; bpv = __ldg(bv + d); }
            float a0 = 0, a1 = 0, a2 = 0, a3 = 0;
#pragma unroll 8
            for (int jj = 0; jj < 256; jj += 4) {
                a0 += hv[jj] * wr[jj];         a1 += hv[jj + 1] * wr[jj + 1];
                a2 += hv[jj + 2] * wr[jj + 2]; a3 += hv[jj + 3] * wr[jj + 3];
            }
            *dst = a0 + a1 + a2 + a3 + bpv;
        }
        HBAR();
        if (htid < 4) {
            float s = 0;
#pragma unroll
            for (int d = 0; d < DK; ++d) s += sq2[half][d] * skk2[half][htid][d];
            ssc2[half][htid] = s * 0.25f;
        }
        HBAR();
        if (htid < 4) {
            float mx = fmaxf(fmaxf(ssc2[half][0], ssc2[half][1]),
                             fmaxf(ssc2[half][2], ssc2[half][3]));
            float sum = expf(ssc2[half][0] - mx) + expf(ssc2[half][1] - mx) +
                        expf(ssc2[half][2] - mx) + expf(ssc2[half][3] - mx);
            sp2[half][htid] = expf(ssc2[half][htid] - mx) / sum;
        }
        HBAR();
        if (htid < DK) {
            float o = 0;
#pragma unroll
            for (int m = 0; m < NB; ++m) o += sp2[half][m] * svv2[half][m][htid];
            so2[half][htid] = o;
        }
        HBAR();
        float v0 = sbfc[htid] + sh[nn2 * 256 + htid];
        float v1 = sbfc[htid + 128] + sh[nn2 * 256 + htid + 128];
#pragma unroll
        for (int d = 0; d < DK; ++d) {
            v0 += so2[half][d] * swfc[htid * DK + d];
            v1 += so2[half][d] * swfc[(htid + 128) * DK + d];
        }
        float s = v0 + v1;
#pragma unroll
        for (int off = 16; off; off >>= 1) s += __shfl_down_sync(0xffffffffu, s, off);
        if (lane == 0) sredh[half][htid >> 5] = s;
        HBAR();
        float mu = (sredh[half][0] + sredh[half][1] + sredh[half][2] + sredh[half][3])
                   * (1.f / BS);
        HBAR();
        float dv0 = v0 - mu, dv1 = v1 - mu;
        float s2 = dv0 * dv0 + dv1 * dv1;
#pragma unroll
        for (int off = 16; off; off >>= 1) s2 += __shfl_down_sync(0xffffffffu, s2, off);
        if (lane == 0) sredh[half][htid >> 5] = s2;
        HBAR();
        float var = (sredh[half][0] + sredh[half][1] + sredh[half][2] + sredh[half][3])
                    * (1.f / BS);
        float rstd = rsqrtf(var + 1e-5f);
        float y0 = dv0 * rstd * slng[htid] + slnb[htid];
        float y1 = dv1 * rstd * slng[htid + 128] + slnb[htid + 128];
        int i0 = bb2 * NHID + nn2 * 256 + htid;
        __stcg(hbuf + i0, y0);       ys_t[i0] = y0;
        __stcg(hbuf + i0 + 128, y1); ys_t[i0 + 128] = y1;

        if (t + 1 < T) {
            const float* xg_t = xg + (size_t)(t + 1) * B * 4096;
#pragma unroll
            for (int bi = 0; bi < 2; ++bi) {
                const float* xr = xg_t + (size_t)(tb2 * 2 + bi) * 4096 + n * 1024 + j;
                xgv[bi][0] = __ldg(xr);       xgv[bi][1] = __ldg(xr + 256);
                xgv[bi][2] = __ldg(xr + 512); xgv[bi][3] = __ldg(xr + 768);
            }
        }
        gbar(bgen);
    }

    {
        int base = (r * 256 + tid) * 2;
        float2 v = __ldcg((const float2*)(hbuf + base));
        *(float2*)(outH + base) = v;
    }
    outC[(tb2 * 2 + 0) * NHID + n * BS + j] = creg[0];
    outC[(tb2 * 2 + 1) * NHID + n * BS + j] = creg[1];
#undef HBAR
}

// ---------------- host driver ------------------------------------------------
extern "C" void kernel_launch(void* const* d_in, const int* in_sizes, int n_in,
                              void* d_out, int out_size) {
    const int* tokens = (const int*)d_in[0];
    const float* h0 = (const float*)d_in[1];
    const float* c0 = (const float*)d_in[2];
    const float* embW = (const float*)d_in[3];
    const float* Wih = (const float*)d_in[4];
    const float* Whh = (const float*)d_in[5];
    const float* bih = (const float*)d_in[6];
    const float* bhh = (const float*)d_in[7];
    const float* wq = (const float*)d_in[8];
    const float* bq = (const float*)d_in[9];
    const float* wk = (const float*)d_in[10];
    const float* bk = (const float*)d_in[11];
    const float* wv = (const float*)d_in[12];
    const float* bv = (const float*)d_in[13];
    const float* wfc = (const float*)d_in[14];
    const float* bfc = (const float*)d_in[15];
    const float* lng = (const float*)d_in[16];
    const float* lnb = (const float*)d_in[17];
    const float* Wd = (const float*)d_in[18];
    const float* bd = (const float*)d_in[19];
    float* out = (float*)d_out;

    static int attr_set = 0;
    if (!attr_set) {
        cudaFuncSetAttribute(k_rec, cudaFuncAttributeMaxDynamicSharedMemorySize,
                             SMEM_REC);
        attr_set = 1;
    }

    float *xb, *xg, *hbuf, *hlbuf;
    unsigned short *wh, *wl, *xh, *xl, *wihh, *wihl;
    cudaGetSymbolAddress((void**)&xb, g_xbuf);
    cudaGetSymbolAddress((void**)&xg, g_xg);
    cudaGetSymbolAddress((void**)&hbuf, g_h);
    cudaGetSymbolAddress((void**)&hlbuf, g_hl);
    cudaGetSymbolAddress((void**)&wh, g_wh);
    cudaGetSymbolAddress((void**)&wl, g_wl);
    cudaGetSymbolAddress((void**)&xh, g_xh);
    cudaGetSymbolAddress((void**)&xl, g_xl);
    cudaGetSymbolAddress((void**)&wihh, g_wihh);
    cudaGetSymbolAddress((void**)&wihl, g_wihl);
    float* x0 = xb;
    float* x1 = xb + (size_t)T * B * NHID;

    // weight conversions (fp16 hi/lo planes)
    k_cvt<<<(int)(((size_t)NTOK * NHID / 4) / 256), 256>>>((const float4*)Wd, wh, wl);
    k_cvt<<<(int)(((size_t)NLAYERS * NB * 4 * BS * NINP / 4) / 256), 256>>>(
        (const float4*)Wih, wihh, wihl);

    k_embed<<<T * B, 256>>>(tokens, embW, x0);

    const size_t DECN = (size_t)T * B * NTOK;
    const size_t WIH_L = (size_t)NB * 4 * BS * NINP;
    for (int l = 0; l < NLAYERS; ++l) {
        const float* xin = (l == 0) ? x0 : x1;
        float* xout = (l == 0) ? x1 : x0;
        const float* Whh_l = Whh + (size_t)l * NB * 4 * BS * BS;
        const float* bih_l = bih + (size_t)l * NB * 4 * BS;
        const float* bhh_l = bhh + (size_t)l * NB * 4 * BS;
        // xg = xin @ Wih_l^T on tensor cores (fp16 3-term)
        k_cvt<<<(int)(((size_t)T * B * NHID / 4) / 256), 256>>>(
            (const float4*)xin, xh, xl);
        k_mma<<<dim3(32, 32), 256>>>(xh, xl, wihh + l * WIH_L, wihl + l * WIH_L,
                                     nullptr, xg, NB * 4 * BS);
        k_rec<<<NCTA, 256, SMEM_REC>>>(xg, Whh_l, bih_l, bhh_l,
                                       h0 + (size_t)l * B * NHID,
                                       c0 + (size_t)l * B * NHID,
                                       wq, bq, wk, bk, wv, bv, wfc, bfc, lng, lnb,
                                       hbuf, hlbuf, xout,
                                       out + DECN + (size_t)l * B * NHID,
                                       out + DECN + (size_t)NLAYERS * B * NHID +
                                           (size_t)l * B * NHID);
    }
    // decoder: out = x0 @ Wd^T + bd (fp16 3-term)
    k_cvt<<<(int)(((size_t)T * B * NHID / 4) / 256), 256>>>((const float4*)x0, xh, xl);
    k_mma<<<dim3(32, 250), 256>>>(xh, xl, wh, wl, bd, out, NTOK);
}